// round 1
// baseline (speedup 1.0000x reference)
#include <cuda_runtime.h>
#include <math.h>

#define Hh 96
#define Ww 128
#define HP 104   // h + 2k
#define WP 136   // w + 2k
#define CIN 128
#define COUT 128
#define NB 2
#define NBR 6

// -------- scratch (device globals: allocation-free) --------
__device__ float g_yg[(size_t)NBR * NB * COUT * HP * WP];  // ~87 MB
__device__ float g_yn[(size_t)NBR * NB * 4 * HP * WP];
__device__ float g_xn[(size_t)NB * 4 * Hh * Ww];

__constant__ int c_rad[6] = {1, 3, 5, 9, 13, 21};

// ---------------- xn = ||xg||_2 over 32-ch groups ----------------
__global__ void xn_kernel(const float* __restrict__ x) {
    int idx = blockIdx.x * blockDim.x + threadIdx.x;
    if (idx >= NB * 4 * Hh * Ww) return;
    int hw = idx % (Hh * Ww);
    int t = idx / (Hh * Ww);
    int g = t % 4, bb = t / 4;
    const float* xp = x + ((size_t)bb * CIN + g * 32) * (Hh * Ww) + hw;
    float s = 0.f;
#pragma unroll
    for (int c = 0; c < 32; c++) { float v = xp[(size_t)c * Hh * Ww]; s += v * v; }
    g_xn[idx] = sqrtf(s);
}

// ---------------- dilated 3x3 conv (fused reflect pad + zero pad) ----------------
// block: 128 cout x (2 rows x 32 cols). 256 threads, each 4co x 8px.
__global__ __launch_bounds__(256) void conv_kernel(const float* __restrict__ y,
                                                   const float* __restrict__ wts,
                                                   const float* __restrict__ bias) {
    int bx = blockIdx.x;            // 0..4  -> x0 = bx*32
    int by = blockIdx.y;            // 0..51 -> oy0 = by*2
    int bz = blockIdx.z;            // branch*2 + bb
    int br = bz >> 1, bb = bz & 1;
    int d = c_rad[br];
    int ws = 32 + 2 * d;            // <= 74
    int x0 = bx * 32, oy0 = by * 2;

    __shared__ float si[4][6][76];
    __shared__ __align__(16) float sw[4][9][128];

    int t = threadIdx.x;
    int tco = t >> 3;               // 0..31
    int tpx = t & 7;
    int r  = tpx >> 2;              // 0..1 (row within tile)
    int cg = tpx & 3;               // 0..3 (8-col group)
    int co = tco * 4;

    float acc[4][8];
#pragma unroll
    for (int a = 0; a < 4; a++) {
        float bv = bias[br * COUT + co + a];
#pragma unroll
        for (int p = 0; p < 8; p++) acc[a][p] = bv;
    }

    const float* ybase = y + (size_t)bb * CIN * Hh * Ww;
    const float* wbase = wts + (size_t)br * COUT * CIN * 9;

    for (int cb = 0; cb < CIN; cb += 4) {
        // weights -> smem, transposed to [ci][tap][co] (coalesced gmem reads)
        for (int idx = t; idx < 4 * 9 * 128; idx += 256) {
            int coI = idx / 36;
            int rem = idx - coI * 36;
            int ci = rem / 9;
            int tap = rem - ci * 9;
            sw[ci][tap][coI] = wbase[(size_t)coI * (CIN * 9) + (cb + ci) * 9 + tap];
        }
        // inputs -> smem, 6 row-slots (2 out-rows x 3 kh), reflect+zero fused
        int n_in = 4 * 6 * ws;
        for (int idx = t; idx < n_in; idx += 256) {
            int ci = idx / (6 * ws);
            int rem = idx - ci * 6 * ws;
            int slot = rem / ws;
            int col = rem - slot * ws;
            int rr = slot / 3, kh = slot - rr * 3;
            int gr = oy0 + rr + d * (kh - 1);      // y_pad row coord
            int gc = x0 - d + col;                 // y_pad col coord
            float v = 0.f;
            if (gr >= 0 && gr < HP && gc >= 0 && gc < WP) {
                int yr = gr - 4; yr = yr < 0 ? -yr : yr; yr = yr >= Hh ? 2 * Hh - 2 - yr : yr;
                int yc = gc - 4; yc = yc < 0 ? -yc : yc; yc = yc >= Ww ? 2 * Ww - 2 - yc : yc;
                v = ybase[(size_t)(cb + ci) * (Hh * Ww) + yr * Ww + yc];
            }
            si[ci][slot][col] = v;
        }
        __syncthreads();

#pragma unroll
        for (int ci = 0; ci < 4; ci++) {
#pragma unroll
            for (int kh = 0; kh < 3; kh++) {
                const float* ip0 = &si[ci][r * 3 + kh][cg * 8];
#pragma unroll
                for (int kw = 0; kw < 3; kw++) {
                    float4 wv = *(const float4*)&sw[ci][kh * 3 + kw][co];
                    const float* ip = ip0 + d * kw;
#pragma unroll
                    for (int p = 0; p < 8; p++) {
                        float v = ip[p];
                        acc[0][p] += wv.x * v;
                        acc[1][p] += wv.y * v;
                        acc[2][p] += wv.z * v;
                        acc[3][p] += wv.w * v;
                    }
                }
            }
        }
        __syncthreads();
    }

    int oy = oy0 + r;
    int ox0 = x0 + cg * 8;
    float* og = g_yg + (size_t)(br * NB + bb) * COUT * HP * WP;
#pragma unroll
    for (int a = 0; a < 4; a++) {
        float* orow = og + (size_t)(co + a) * HP * WP + (size_t)oy * WP + ox0;
#pragma unroll
        for (int p = 0; p < 8; p++)
            if (ox0 + p < WP) orow[p] = acc[a][p];
    }
}

// ---------------- yn = ||yg||_2 over 32-ch groups ----------------
__global__ void yn_kernel() {
    int idx = blockIdx.x * blockDim.x + threadIdx.x;
    if (idx >= NBR * NB * 4 * HP * WP) return;
    int hw = idx % (HP * WP);
    int t = idx / (HP * WP);
    int g = t % 4; t /= 4;
    int bb = t % 2; int br = t / 2;
    const float* p = g_yg + ((size_t)(br * NB + bb) * COUT + g * 32) * HP * WP + hw;
    float s = 0.f;
#pragma unroll
    for (int c = 0; c < 32; c++) { float v = p[(size_t)c * HP * WP]; s += v * v; }
    g_yn[idx] = sqrtf(s);
}

// ---------------- 81-shift grouped correlation ----------------
// block: 16x16 pixel tile, one (b, g, branch). xg cached in regs, yg from smem.
__global__ __launch_bounds__(256, 2) void corr_kernel(const float* __restrict__ x,
                                                      float* __restrict__ out) {
    int bz = blockIdx.z;                 // ((bb*4+g)*6 + br)
    int br = bz % 6; int t2 = bz / 6;
    int g = t2 & 3; int bb = t2 >> 2;
    int hx0 = blockIdx.x * 16, hy0 = blockIdx.y * 16;
    int tx = threadIdx.x & 15, ty = threadIdx.x >> 4;

    __shared__ float syg[8][24][25];
    __shared__ float sxg[8][16][16];
    __shared__ float syn[24][25];

    const float* ygb = g_yg + ((size_t)(br * NB + bb) * COUT + g * 32) * HP * WP;
    const float* xgb = x + ((size_t)bb * CIN + g * 32) * Hh * Ww;

    float acc[81];
#pragma unroll
    for (int s = 0; s < 81; s++) acc[s] = 0.f;

    for (int cb = 0; cb < 32; cb += 8) {
        for (int idx = threadIdx.x; idx < 8 * 24 * 24; idx += 256) {
            int c = idx / 576; int rem = idx - c * 576;
            int rr = rem / 24; int cc = rem - rr * 24;
            syg[c][rr][cc] = ygb[(size_t)(cb + c) * HP * WP + (size_t)(hy0 + rr) * WP + hx0 + cc];
        }
        for (int idx = threadIdx.x; idx < 8 * 16 * 16; idx += 256) {
            int c = idx >> 8; int rem = idx & 255;
            int rr = rem >> 4; int cc = rem & 15;
            sxg[c][rr][cc] = xgb[(size_t)(cb + c) * Hh * Ww + (size_t)(hy0 + rr) * Ww + hx0 + cc];
        }
        __syncthreads();
        float xr[8];
#pragma unroll
        for (int c = 0; c < 8; c++) xr[c] = sxg[c][ty][tx];
#pragma unroll
        for (int sx = 0; sx < 9; sx++) {
#pragma unroll
            for (int sy = 0; sy < 9; sy++) {
                float dsum = 0.f;
#pragma unroll
                for (int c = 0; c < 8; c++)
                    dsum += xr[c] * syg[c][ty + sx][tx + sy];
                acc[sx * 9 + sy] += dsum;
            }
        }
        __syncthreads();
    }

    for (int idx = threadIdx.x; idx < 24 * 24; idx += 256) {
        int rr = idx / 24, cc = idx - rr * 24;
        syn[rr][cc] = g_yn[(((size_t)br * NB + bb) * 4 + g) * HP * WP + (size_t)(hy0 + rr) * WP + hx0 + cc];
    }
    __syncthreads();

    float xnv = g_xn[((size_t)bb * 4 + g) * Hh * Ww + (size_t)(hy0 + ty) * Ww + hx0 + tx];
    size_t obase = ((size_t)(bb * 24 + br * 4 + g) * 81) * (Hh * Ww)
                 + (size_t)(hy0 + ty) * Ww + (hx0 + tx);
#pragma unroll
    for (int sx = 0; sx < 9; sx++) {
#pragma unroll
        for (int sy = 0; sy < 9; sy++) {
            float den = fmaxf(xnv * syn[ty + sx][tx + sy], 1e-8f);
            out[obase + (size_t)(sx * 9 + sy) * (Hh * Ww)] = acc[sx * 9 + sy] / den;
        }
    }
}

// ---------------- launch ----------------
extern "C" void kernel_launch(void* const* d_in, const int* in_sizes, int n_in,
                              void* d_out, int out_size) {
    const float* x    = (const float*)d_in[0];
    const float* y    = (const float*)d_in[1];
    const float* wts  = (const float*)d_in[2];
    const float* bias = (const float*)d_in[3];
    float* out = (float*)d_out;

    xn_kernel<<<(NB * 4 * Hh * Ww + 255) / 256, 256>>>(x);
    conv_kernel<<<dim3(5, 52, NBR * NB), 256>>>(y, wts, bias);
    yn_kernel<<<(NBR * NB * 4 * HP * WP + 255) / 256, 256>>>();
    corr_kernel<<<dim3(Ww / 16, Hh / 16, NB * 4 * NBR), 256>>>(x, out);
}

// round 3
// speedup vs baseline: 2.7479x; 2.7479x over previous
#include <cuda_runtime.h>
#include <math.h>
#include <cstdint>

#define Hh 96
#define Ww 128
#define HP 104
#define WP 136
#define CIN 128
#define COUT 128
#define NB 2
#define NBR 6
#define EXH 146            // HP + 2*21
#define EXW 178            // WP + 2*21
#define EXHW (EXH*EXW)

// -------- scratch (device globals: allocation-free) --------
__device__ float g_yg[(size_t)NBR * NB * COUT * HP * WP];   // ~87 MB
__device__ float g_yn[(size_t)NBR * NB * 4 * HP * WP];
__device__ float g_xn[(size_t)NB * 4 * Hh * Ww];
__device__ float g_yext[(size_t)NB * CIN * EXHW];           // ~26.6 MB
__device__ float g_wA[(size_t)NBR * 9 * COUT * CIN];        // 3.5 MB

__constant__ int c_rad[6] = {1, 3, 5, 9, 13, 21};

__device__ __forceinline__ float tf32r(float x) {
    uint32_t u;
    asm("cvt.rna.tf32.f32 %0, %1;" : "=r"(u) : "f"(x));
    return __uint_as_float(u);
}
__device__ __forceinline__ void mma8(float* c, const uint32_t* a, uint32_t b0, uint32_t b1) {
    asm volatile(
        "mma.sync.aligned.m16n8k8.row.col.f32.tf32.tf32.f32 "
        "{%0,%1,%2,%3}, {%4,%5,%6,%7}, {%8,%9}, {%0,%1,%2,%3};"
        : "+f"(c[0]), "+f"(c[1]), "+f"(c[2]), "+f"(c[3])
        : "r"(a[0]), "r"(a[1]), "r"(a[2]), "r"(a[3]), "r"(b0), "r"(b1));
}

// ---------------- y_ext: reflect pad + 21 zero halo ----------------
__global__ void pad_kernel(const float* __restrict__ y) {
    int idx = blockIdx.x * blockDim.x + threadIdx.x;
    if (idx >= NB * CIN * EXHW) return;
    int c = idx % EXW; int t = idx / EXW;
    int rr = t % EXH; t /= EXH;
    int ci = t % CIN; int bb = t / CIN;
    int pr = rr - 21, pc = c - 21;
    float v = 0.f;
    if (pr >= 0 && pr < HP && pc >= 0 && pc < WP) {
        int yr = pr - 4; yr = yr < 0 ? -yr : yr; yr = yr >= Hh ? 2 * Hh - 2 - yr : yr;
        int yc = pc - 4; yc = yc < 0 ? -yc : yc; yc = yc >= Ww ? 2 * Ww - 2 - yc : yc;
        v = y[((size_t)bb * CIN + ci) * (Hh * Ww) + (size_t)yr * Ww + yc];
    }
    g_yext[idx] = v;
}

// ---------------- weight transform: wA[br][tap][co][ci] ----------------
__global__ void wt_kernel(const float* __restrict__ w) {
    int idx = blockIdx.x * blockDim.x + threadIdx.x;
    if (idx >= NBR * 9 * COUT * CIN) return;
    int ci = idx % CIN; int t = idx / CIN;
    int co = t % COUT; t /= COUT;
    int tap = t % 9; int br = t / 9;
    g_wA[idx] = w[(((size_t)br * COUT + co) * CIN + ci) * 9 + tap];
}

// ---------------- xn ----------------
__global__ void xn_kernel(const float* __restrict__ x) {
    int idx = blockIdx.x * blockDim.x + threadIdx.x;
    if (idx >= NB * 4 * Hh * Ww) return;
    int hw = idx % (Hh * Ww);
    int t = idx / (Hh * Ww);
    int g = t % 4, bb = t / 4;
    const float* xp = x + ((size_t)bb * CIN + g * 32) * (Hh * Ww) + hw;
    float s = 0.f;
#pragma unroll
    for (int c = 0; c < 32; c++) { float v = xp[(size_t)c * Hh * Ww]; s += v * v; }
    g_xn[idx] = sqrtf(s);
}

// ---------------- tf32 mma.sync conv ----------------
// CTA: one output row (136 px) x 128 cout, K = 1152.
// Warps: 4 in M (32 co each) x 2 in N (tiles 0-8 / 9-16).
#define LDA 36
#define LDB 140

__global__ __launch_bounds__(256) void conv_mma_kernel(const float* __restrict__ bias) {
    __shared__ float sA[128 * LDA];   // 18432 B
    __shared__ float sB[32 * LDB];    // 17920 B

    int tid = threadIdx.x, warp = tid >> 5, lane = tid & 31;
    int gq = lane >> 2, tig = lane & 3;
    int br = blockIdx.y >> 1, bb = blockIdx.y & 1;
    int r = blockIdx.x;               // 0..103
    int d = c_rad[br];
    int wm = warp & 3, wn = warp >> 2;
    int ntiles = wn ? 8 : 9;
    int tbase = wn * 9;

    float acc[2][9][4];
#pragma unroll
    for (int mt = 0; mt < 2; mt++)
#pragma unroll
        for (int t = 0; t < 9; t++)
#pragma unroll
            for (int u = 0; u < 4; u++) acc[mt][t][u] = 0.f;

    const float* wbr = g_wA + (size_t)br * 9 * COUT * CIN;
    const float* yb  = g_yext + (size_t)bb * CIN * EXHW;

    for (int tap = 0; tap < 9; tap++) {
        int kh = tap / 3, kw = tap - kh * 3;
        const float* ysrc = yb + (size_t)(r + 21 + d * (kh - 1)) * EXW + (21 + d * (kw - 1));
        const float* wtap = wbr + (size_t)tap * COUT * CIN;
        for (int q = 0; q < 4; q++) {
            __syncthreads();
            // stage A: [128co][32ci] (lda=36, conflict-free frags)
            const float4* wsrc = (const float4*)(wtap + q * 32);
            for (int i = tid; i < 1024; i += 256) {
                int co = i >> 3, k4 = i & 7;
                float4 v = wsrc[co * 32 + k4];
                v.x = tf32r(v.x); v.y = tf32r(v.y); v.z = tf32r(v.z); v.w = tf32r(v.w);
                *(float4*)&sA[co * LDA + k4 * 4] = v;
            }
            // stage B: [32ci][136px] (ldb=140, conflict-free frags)
            for (int i = tid; i < 4352; i += 256) {
                int k = i / 136, n = i - k * 136;
                sB[k * LDB + n] = tf32r(ysrc[(size_t)(q * 32 + k) * EXHW + n]);
            }
            __syncthreads();
#pragma unroll
            for (int kk = 0; kk < 32; kk += 8) {
                uint32_t a[2][4];
#pragma unroll
                for (int mt = 0; mt < 2; mt++) {
                    int row = wm * 32 + mt * 16 + gq;
                    a[mt][0] = __float_as_uint(sA[row * LDA + kk + tig]);
                    a[mt][1] = __float_as_uint(sA[(row + 8) * LDA + kk + tig]);
                    a[mt][2] = __float_as_uint(sA[row * LDA + kk + tig + 4]);
                    a[mt][3] = __float_as_uint(sA[(row + 8) * LDA + kk + tig + 4]);
                }
#pragma unroll
                for (int t = 0; t < 9; t++) {
                    if (t < ntiles) {
                        int col = (tbase + t) * 8 + gq;
                        uint32_t b0 = __float_as_uint(sB[(kk + tig) * LDB + col]);
                        uint32_t b1 = __float_as_uint(sB[(kk + tig + 4) * LDB + col]);
                        mma8(acc[0][t], a[0], b0, b1);
                        mma8(acc[1][t], a[1], b0, b1);
                    }
                }
            }
        }
    }

    // epilogue: bias + store to g_yg
    float* og = g_yg + (size_t)(br * NB + bb) * COUT * HP * WP + (size_t)r * WP;
#pragma unroll
    for (int mt = 0; mt < 2; mt++) {
        int co0 = wm * 32 + mt * 16 + gq, co1 = co0 + 8;
        float bv0 = bias[br * COUT + co0], bv1 = bias[br * COUT + co1];
#pragma unroll
        for (int t = 0; t < 9; t++) {
            if (t < ntiles) {
                int col = (tbase + t) * 8 + 2 * tig;
                *(float2*)&og[(size_t)co0 * HP * WP + col] =
                    make_float2(acc[mt][t][0] + bv0, acc[mt][t][1] + bv0);
                *(float2*)&og[(size_t)co1 * HP * WP + col] =
                    make_float2(acc[mt][t][2] + bv1, acc[mt][t][3] + bv1);
            }
        }
    }
}

// ---------------- yn ----------------
__global__ void yn_kernel() {
    int idx = blockIdx.x * blockDim.x + threadIdx.x;
    if (idx >= NBR * NB * 4 * HP * WP) return;
    int hw = idx % (HP * WP);
    int t = idx / (HP * WP);
    int g = t % 4; t /= 4;
    int bb = t % 2; int br = t / 2;
    const float* p = g_yg + ((size_t)(br * NB + bb) * COUT + g * 32) * HP * WP + hw;
    float s = 0.f;
#pragma unroll
    for (int c = 0; c < 32; c++) { float v = p[(size_t)c * HP * WP]; s += v * v; }
    g_yn[idx] = sqrtf(s);
}

// ---------------- 81-shift grouped correlation ----------------
__global__ __launch_bounds__(256, 2) void corr_kernel(const float* __restrict__ x,
                                                      float* __restrict__ out) {
    int bz = blockIdx.z;
    int br = bz % 6; int t2 = bz / 6;
    int g = t2 & 3; int bb = t2 >> 2;
    int hx0 = blockIdx.x * 16, hy0 = blockIdx.y * 16;
    int tx = threadIdx.x & 15, ty = threadIdx.x >> 4;

    __shared__ float syg[8][24][25];
    __shared__ float sxg[8][16][16];
    __shared__ float syn[24][25];

    const float* ygb = g_yg + ((size_t)(br * NB + bb) * COUT + g * 32) * HP * WP;
    const float* xgb = x + ((size_t)bb * CIN + g * 32) * Hh * Ww;

    float acc[81];
#pragma unroll
    for (int s = 0; s < 81; s++) acc[s] = 0.f;

    for (int cb = 0; cb < 32; cb += 8) {
        for (int idx = threadIdx.x; idx < 8 * 24 * 24; idx += 256) {
            int c = idx / 576; int rem = idx - c * 576;
            int rr = rem / 24; int cc = rem - rr * 24;
            syg[c][rr][cc] = ygb[(size_t)(cb + c) * HP * WP + (size_t)(hy0 + rr) * WP + hx0 + cc];
        }
        for (int idx = threadIdx.x; idx < 8 * 16 * 16; idx += 256) {
            int c = idx >> 8; int rem = idx & 255;
            int rr = rem >> 4; int cc = rem & 15;
            sxg[c][rr][cc] = xgb[(size_t)(cb + c) * Hh * Ww + (size_t)(hy0 + rr) * Ww + hx0 + cc];
        }
        __syncthreads();
        float xr[8];
#pragma unroll
        for (int c = 0; c < 8; c++) xr[c] = sxg[c][ty][tx];
#pragma unroll
        for (int sx = 0; sx < 9; sx++) {
#pragma unroll
            for (int sy = 0; sy < 9; sy++) {
                float dsum = 0.f;
#pragma unroll
                for (int c = 0; c < 8; c++)
                    dsum += xr[c] * syg[c][ty + sx][tx + sy];
                acc[sx * 9 + sy] += dsum;
            }
        }
        __syncthreads();
    }

    for (int idx = threadIdx.x; idx < 24 * 24; idx += 256) {
        int rr = idx / 24, cc = idx - rr * 24;
        syn[rr][cc] = g_yn[(((size_t)br * NB + bb) * 4 + g) * HP * WP + (size_t)(hy0 + rr) * WP + hx0 + cc];
    }
    __syncthreads();

    float xnv = g_xn[((size_t)bb * 4 + g) * Hh * Ww + (size_t)(hy0 + ty) * Ww + hx0 + tx];
    size_t obase = ((size_t)(bb * 24 + br * 4 + g) * 81) * (Hh * Ww)
                 + (size_t)(hy0 + ty) * Ww + (hx0 + tx);
#pragma unroll
    for (int sx = 0; sx < 9; sx++) {
#pragma unroll
        for (int sy = 0; sy < 9; sy++) {
            float den = fmaxf(xnv * syn[ty + sx][tx + sy], 1e-8f);
            out[obase + (size_t)(sx * 9 + sy) * (Hh * Ww)] = acc[sx * 9 + sy] / den;
        }
    }
}

// ---------------- launch ----------------
extern "C" void kernel_launch(void* const* d_in, const int* in_sizes, int n_in,
                              void* d_out, int out_size) {
    const float* x    = (const float*)d_in[0];
    const float* y    = (const float*)d_in[1];
    const float* wts  = (const float*)d_in[2];
    const float* bias = (const float*)d_in[3];
    float* out = (float*)d_out;

    pad_kernel<<<(NB * CIN * EXHW + 255) / 256, 256>>>(y);
    wt_kernel<<<(NBR * 9 * COUT * CIN + 255) / 256, 256>>>(wts);
    xn_kernel<<<(NB * 4 * Hh * Ww + 255) / 256, 256>>>(x);
    conv_mma_kernel<<<dim3(104, 12), 256>>>(bias);
    yn_kernel<<<(NBR * NB * 4 * HP * WP + 255) / 256, 256>>>();
    corr_kernel<<<dim3(Ww / 16, Hh / 16, NB * 4 * NBR), 256>>>(x, out);
}

// round 4
// speedup vs baseline: 4.3696x; 1.5902x over previous
#include <cuda_runtime.h>
#include <math.h>
#include <cstdint>

#define Hh 96
#define Ww 128
#define HP 104
#define WP 136
#define CIN 128
#define COUT 128
#define NB 2
#define NBR 6
#define EXH 146            // HP + 2*21
#define EXW 178            // WP + 2*21
#define EXHW (EXH*EXW)

// -------- scratch (device globals: allocation-free) --------
__device__ float g_yg[(size_t)NBR * NB * COUT * HP * WP];   // ~87 MB
__device__ float g_yn[(size_t)NBR * NB * 4 * HP * WP];
__device__ float g_xn[(size_t)NB * 4 * Hh * Ww];
__device__ float g_yext[(size_t)NB * CIN * EXHW];           // ~26.6 MB (pre-rounded tf32)
__device__ float g_wA[(size_t)NBR * 9 * COUT * CIN];        // 3.5 MB  (pre-rounded tf32)

__constant__ int c_rad[6] = {1, 3, 5, 9, 13, 21};

__device__ __forceinline__ float tf32r(float x) {
    uint32_t u;
    asm("cvt.rna.tf32.f32 %0, %1;" : "=r"(u) : "f"(x));
    return __uint_as_float(u);
}
__device__ __forceinline__ void mma8(float* c, const uint32_t* a, uint32_t b0, uint32_t b1) {
    asm volatile(
        "mma.sync.aligned.m16n8k8.row.col.f32.tf32.tf32.f32 "
        "{%0,%1,%2,%3}, {%4,%5,%6,%7}, {%8,%9}, {%0,%1,%2,%3};"
        : "+f"(c[0]), "+f"(c[1]), "+f"(c[2]), "+f"(c[3])
        : "r"(a[0]), "r"(a[1]), "r"(a[2]), "r"(a[3]), "r"(b0), "r"(b1));
}
__device__ __forceinline__ void cpa16(float* dst, const float* src) {
    uint32_t d = (uint32_t)__cvta_generic_to_shared(dst);
    asm volatile("cp.async.cg.shared.global [%0], [%1], 16;" :: "r"(d), "l"(src));
}
__device__ __forceinline__ void cpa4(float* dst, const float* src) {
    uint32_t d = (uint32_t)__cvta_generic_to_shared(dst);
    asm volatile("cp.async.ca.shared.global [%0], [%1], 4;" :: "r"(d), "l"(src));
}
#define CP_COMMIT() asm volatile("cp.async.commit_group;" ::: "memory")

// ---------------- y_ext: reflect pad + 21 zero halo (tf32 pre-round) ----------------
__global__ void pad_kernel(const float* __restrict__ y) {
    int idx = blockIdx.x * blockDim.x + threadIdx.x;
    if (idx >= NB * CIN * EXHW) return;
    int c = idx % EXW; int t = idx / EXW;
    int rr = t % EXH; t /= EXH;
    int ci = t % CIN; int bb = t / CIN;
    int pr = rr - 21, pc = c - 21;
    float v = 0.f;
    if (pr >= 0 && pr < HP && pc >= 0 && pc < WP) {
        int yr = pr - 4; yr = yr < 0 ? -yr : yr; yr = yr >= Hh ? 2 * Hh - 2 - yr : yr;
        int yc = pc - 4; yc = yc < 0 ? -yc : yc; yc = yc >= Ww ? 2 * Ww - 2 - yc : yc;
        v = tf32r(y[((size_t)bb * CIN + ci) * (Hh * Ww) + (size_t)yr * Ww + yc]);
    }
    g_yext[idx] = v;
}

// ---------------- weight transform: wA[br][tap][co][ci], tf32 pre-round ----------------
__global__ void wt_kernel(const float* __restrict__ w) {
    int idx = blockIdx.x * blockDim.x + threadIdx.x;
    if (idx >= NBR * 9 * COUT * CIN) return;
    int ci = idx % CIN; int t = idx / CIN;
    int co = t % COUT; t /= COUT;
    int tap = t % 9; int br = t / 9;
    g_wA[idx] = tf32r(w[(((size_t)br * COUT + co) * CIN + ci) * 9 + tap]);
}

// ---------------- xn ----------------
__global__ void xn_kernel(const float* __restrict__ x) {
    int idx = blockIdx.x * blockDim.x + threadIdx.x;
    if (idx >= NB * 4 * Hh * Ww) return;
    int hw = idx % (Hh * Ww);
    int t = idx / (Hh * Ww);
    int g = t % 4, bb = t / 4;
    const float* xp = x + ((size_t)bb * CIN + g * 32) * (Hh * Ww) + hw;
    float s = 0.f;
#pragma unroll
    for (int c = 0; c < 32; c++) { float v = xp[(size_t)c * Hh * Ww]; s += v * v; }
    g_xn[idx] = sqrtf(s);
}

// ---------------- tf32 mma.sync conv, cp.async double-buffered ----------------
#define LDA 36
#define LDB 152
#define SB_OFF 4608          // floats: 128*36
#define STG 9472             // floats per stage: 4608 + 32*152
#define CONV_SMEM (2 * STG * 4)

__device__ __forceinline__ void stage_tile(float* buf, int it, int tid,
                                           const float* wbr, const float* yb,
                                           int r, int d) {
    int tap = it >> 2, q = it & 3;
    int kh = tap / 3, kw = tap - kh * 3;
    // A: [128co][32ci], 16B chunks, dst 16B aligned (LDA*4=144B rows)
    const float* wsrc = wbr + (size_t)tap * COUT * CIN + q * 32;
#pragma unroll
    for (int i = tid; i < 1024; i += 256) {
        int co = i >> 3, k4 = i & 7;
        cpa16(buf + co * LDA + k4 * 4, wsrc + (size_t)co * CIN + k4 * 4);
    }
    // B: [32ci][136px], 4B chunks (row bases not 16B aligned)
    const float* ysrc = yb + (size_t)q * 32 * EXHW
                      + (size_t)(r + 21 + d * (kh - 1)) * EXW + (21 + d * (kw - 1));
    int kr = tid >> 3, cc0 = tid & 7;
    const float* rowp = ysrc + (size_t)kr * EXHW + cc0;
    float* dstrow = buf + SB_OFF + kr * LDB + cc0;
#pragma unroll
    for (int c = 0; c < 17; c++) cpa4(dstrow + c * 8, rowp + c * 8);
}

__global__ __launch_bounds__(256, 2) void conv_mma_kernel(const float* __restrict__ bias) {
    extern __shared__ float smem[];
    int tid = threadIdx.x, warp = tid >> 5, lane = tid & 31;
    int gq = lane >> 2, tig = lane & 3;
    int br = blockIdx.y >> 1, bb = blockIdx.y & 1;
    int r = blockIdx.x;
    int d = c_rad[br];
    int wm = warp & 3, wn = warp >> 2;
    int ntiles = wn ? 8 : 9;
    int tbase = wn * 9;

    const float* wbr = g_wA + (size_t)br * 9 * COUT * CIN;
    const float* yb  = g_yext + (size_t)bb * CIN * EXHW;

    float acc[2][9][4];
#pragma unroll
    for (int mt = 0; mt < 2; mt++)
#pragma unroll
        for (int t = 0; t < 9; t++)
#pragma unroll
            for (int u = 0; u < 4; u++) acc[mt][t][u] = 0.f;

    stage_tile(smem, 0, tid, wbr, yb, r, d);
    CP_COMMIT();

    for (int it = 0; it < 36; ++it) {
        if (it < 35) {
            stage_tile(smem + ((it + 1) & 1) * STG, it + 1, tid, wbr, yb, r, d);
            CP_COMMIT();
            asm volatile("cp.async.wait_group 1;" ::: "memory");
        } else {
            asm volatile("cp.async.wait_group 0;" ::: "memory");
        }
        __syncthreads();
        const float* sA = smem + (it & 1) * STG;
        const float* sB = sA + SB_OFF;
#pragma unroll
        for (int kk = 0; kk < 32; kk += 8) {
            uint32_t a[2][4];
#pragma unroll
            for (int mt = 0; mt < 2; mt++) {
                int row = wm * 32 + mt * 16 + gq;
                a[mt][0] = __float_as_uint(sA[row * LDA + kk + tig]);
                a[mt][1] = __float_as_uint(sA[(row + 8) * LDA + kk + tig]);
                a[mt][2] = __float_as_uint(sA[row * LDA + kk + tig + 4]);
                a[mt][3] = __float_as_uint(sA[(row + 8) * LDA + kk + tig + 4]);
            }
#pragma unroll
            for (int t = 0; t < 9; t++) {
                if (t < ntiles) {
                    int col = (tbase + t) * 8 + gq;
                    uint32_t b0 = __float_as_uint(sB[(kk + tig) * LDB + col]);
                    uint32_t b1 = __float_as_uint(sB[(kk + tig + 4) * LDB + col]);
                    mma8(acc[0][t], a[0], b0, b1);
                    mma8(acc[1][t], a[1], b0, b1);
                }
            }
        }
        __syncthreads();
    }

    // epilogue: bias + store to g_yg
    float* og = g_yg + (size_t)(br * NB + bb) * COUT * HP * WP + (size_t)r * WP;
#pragma unroll
    for (int mt = 0; mt < 2; mt++) {
        int co0 = wm * 32 + mt * 16 + gq, co1 = co0 + 8;
        float bv0 = bias[br * COUT + co0], bv1 = bias[br * COUT + co1];
#pragma unroll
        for (int t = 0; t < 9; t++) {
            if (t < ntiles) {
                int col = (tbase + t) * 8 + 2 * tig;
                *(float2*)&og[(size_t)co0 * HP * WP + col] =
                    make_float2(acc[mt][t][0] + bv0, acc[mt][t][1] + bv0);
                *(float2*)&og[(size_t)co1 * HP * WP + col] =
                    make_float2(acc[mt][t][2] + bv1, acc[mt][t][3] + bv1);
            }
        }
    }
}

// ---------------- yn ----------------
__global__ void yn_kernel() {
    int idx = blockIdx.x * blockDim.x + threadIdx.x;
    if (idx >= NBR * NB * 4 * HP * WP) return;
    int hw = idx % (HP * WP);
    int t = idx / (HP * WP);
    int g = t % 4; t /= 4;
    int bb = t % 2; int br = t / 2;
    const float* p = g_yg + ((size_t)(br * NB + bb) * COUT + g * 32) * HP * WP + hw;
    float s = 0.f;
#pragma unroll
    for (int c = 0; c < 32; c++) { float v = p[(size_t)c * HP * WP]; s += v * v; }
    g_yn[idx] = sqrtf(s);
}

// ---------------- 81-shift grouped correlation (float2 channel pairs) ----------------
__global__ __launch_bounds__(256, 2) void corr_kernel(const float* __restrict__ x,
                                                      float* __restrict__ out) {
    int bz = blockIdx.z;
    int br = bz % 6; int t2 = bz / 6;
    int g = t2 & 3; int bb = t2 >> 2;
    int hx0 = blockIdx.x * 16, hy0 = blockIdx.y * 16;
    int tx = threadIdx.x & 15, ty = threadIdx.x >> 4;

    __shared__ float2 syg2[4][24][25];
    __shared__ float2 sxg2[4][16][17];
    __shared__ float syn[24][25];

    const float* ygb = g_yg + ((size_t)(br * NB + bb) * COUT + g * 32) * HP * WP;
    const float* xgb = x + ((size_t)bb * CIN + g * 32) * Hh * Ww;

    float acc[81];
#pragma unroll
    for (int s = 0; s < 81; s++) acc[s] = 0.f;

    for (int cb = 0; cb < 32; cb += 8) {
        for (int idx = threadIdx.x; idx < 4 * 24 * 24; idx += 256) {
            int cp = idx / 576; int rem = idx - cp * 576;
            int rr = rem / 24; int cc = rem - rr * 24;
            const float* p = ygb + (size_t)(cb + 2 * cp) * HP * WP
                           + (size_t)(hy0 + rr) * WP + hx0 + cc;
            syg2[cp][rr][cc] = make_float2(p[0], p[HP * WP]);
        }
        for (int idx = threadIdx.x; idx < 4 * 16 * 16; idx += 256) {
            int cp = idx >> 8; int rem = idx & 255;
            int rr = rem >> 4; int cc = rem & 15;
            const float* p = xgb + (size_t)(cb + 2 * cp) * Hh * Ww
                           + (size_t)(hy0 + rr) * Ww + hx0 + cc;
            sxg2[cp][rr][cc] = make_float2(p[0], p[Hh * Ww]);
        }
        __syncthreads();
        float2 xr[4];
#pragma unroll
        for (int cp = 0; cp < 4; cp++) xr[cp] = sxg2[cp][ty][tx];
#pragma unroll
        for (int sx = 0; sx < 9; sx++) {
#pragma unroll
            for (int sy = 0; sy < 9; sy++) {
                float dsum = 0.f;
#pragma unroll
                for (int cp = 0; cp < 4; cp++) {
                    float2 yv = syg2[cp][ty + sx][tx + sy];
                    dsum += xr[cp].x * yv.x;
                    dsum += xr[cp].y * yv.y;
                }
                acc[sx * 9 + sy] += dsum;
            }
        }
        __syncthreads();
    }

    for (int idx = threadIdx.x; idx < 24 * 24; idx += 256) {
        int rr = idx / 24, cc = idx - rr * 24;
        syn[rr][cc] = g_yn[(((size_t)br * NB + bb) * 4 + g) * HP * WP
                           + (size_t)(hy0 + rr) * WP + hx0 + cc];
    }
    __syncthreads();

    float xnv = g_xn[((size_t)bb * 4 + g) * Hh * Ww + (size_t)(hy0 + ty) * Ww + hx0 + tx];
    size_t obase = ((size_t)(bb * 24 + br * 4 + g) * 81) * (Hh * Ww)
                 + (size_t)(hy0 + ty) * Ww + (hx0 + tx);
#pragma unroll
    for (int sx = 0; sx < 9; sx++) {
#pragma unroll
        for (int sy = 0; sy < 9; sy++) {
            float den = fmaxf(xnv * syn[ty + sx][tx + sy], 1e-8f);
            out[obase + (size_t)(sx * 9 + sy) * (Hh * Ww)] = acc[sx * 9 + sy] / den;
        }
    }
}

// ---------------- launch ----------------
extern "C" void kernel_launch(void* const* d_in, const int* in_sizes, int n_in,
                              void* d_out, int out_size) {
    const float* x    = (const float*)d_in[0];
    const float* y    = (const float*)d_in[1];
    const float* wts  = (const float*)d_in[2];
    const float* bias = (const float*)d_in[3];
    float* out = (float*)d_out;

    cudaFuncSetAttribute(conv_mma_kernel,
                         cudaFuncAttributeMaxDynamicSharedMemorySize, CONV_SMEM);

    pad_kernel<<<(NB * CIN * EXHW + 255) / 256, 256>>>(y);
    wt_kernel<<<(NBR * 9 * COUT * CIN + 255) / 256, 256>>>(wts);
    xn_kernel<<<(NB * 4 * Hh * Ww + 255) / 256, 256>>>(x);
    conv_mma_kernel<<<dim3(104, 12), 256, CONV_SMEM>>>(bias);
    yn_kernel<<<(NBR * NB * 4 * HP * WP + 255) / 256, 256>>>();
    corr_kernel<<<dim3(Ww / 16, Hh / 16, NB * 4 * NBR), 256>>>(x, out);
}

// round 5
// speedup vs baseline: 6.0807x; 1.3916x over previous
#include <cuda_runtime.h>
#include <cuda_fp16.h>
#include <math.h>
#include <cstdint>

#define Hh 96
#define Ww 128
#define HP 104
#define WP 136
#define CIN 128
#define COUT 128
#define NB 2
#define NBR 6
#define EXH 146            // HP + 2*21
#define EXW 178            // WP + 2*21
#define EXHW (EXH*EXW)

// -------- scratch (device globals: allocation-free) --------
__device__ float g_yg[(size_t)NBR * NB * COUT * HP * WP];    // ~87 MB
__device__ float g_yn[(size_t)NBR * NB * 4 * HP * WP];
__device__ float g_xn[(size_t)NB * 4 * Hh * Ww];
__device__ __half2 g_yext2[(size_t)NB * 64 * EXHW];          // ci-pair interleaved fp16
__device__ __half g_wAh[(size_t)NBR * 9 * COUT * CIN];       // fp16 weights [br][tap][co][ci]

__constant__ int c_rad[6] = {1, 3, 5, 9, 13, 21};

__device__ __forceinline__ void mma16(float* c, const uint32_t* a, uint32_t b0, uint32_t b1) {
    asm volatile(
        "mma.sync.aligned.m16n8k16.row.col.f32.f16.f16.f32 "
        "{%0,%1,%2,%3}, {%4,%5,%6,%7}, {%8,%9}, {%0,%1,%2,%3};"
        : "+f"(c[0]), "+f"(c[1]), "+f"(c[2]), "+f"(c[3])
        : "r"(a[0]), "r"(a[1]), "r"(a[2]), "r"(a[3]), "r"(b0), "r"(b1));
}
__device__ __forceinline__ void cpa16(void* dst, const void* src) {
    uint32_t d = (uint32_t)__cvta_generic_to_shared(dst);
    asm volatile("cp.async.cg.shared.global [%0], [%1], 16;" :: "r"(d), "l"(src));
}
__device__ __forceinline__ void cpa4(void* dst, const void* src) {
    uint32_t d = (uint32_t)__cvta_generic_to_shared(dst);
    asm volatile("cp.async.ca.shared.global [%0], [%1], 4;" :: "r"(d), "l"(src));
}
#define CP_COMMIT() asm volatile("cp.async.commit_group;" ::: "memory")

// ---------------- y_ext fp16 half2 (ci pairs): reflect pad + 21 zero halo ----------------
__global__ void pad_kernel(const float* __restrict__ y) {
    int idx = blockIdx.x * blockDim.x + threadIdx.x;
    if (idx >= NB * 64 * EXHW) return;
    int c = idx % EXW; int t = idx / EXW;
    int rr = t % EXH; t /= EXH;
    int cp = t % 64; int bb = t / 64;
    int pr = rr - 21, pc = c - 21;
    float v0 = 0.f, v1 = 0.f;
    if (pr >= 0 && pr < HP && pc >= 0 && pc < WP) {
        int yr = pr - 4; yr = yr < 0 ? -yr : yr; yr = yr >= Hh ? 2 * Hh - 2 - yr : yr;
        int yc = pc - 4; yc = yc < 0 ? -yc : yc; yc = yc >= Ww ? 2 * Ww - 2 - yc : yc;
        const float* p = y + ((size_t)bb * CIN + 2 * cp) * (Hh * Ww) + (size_t)yr * Ww + yc;
        v0 = p[0]; v1 = p[Hh * Ww];
    }
    g_yext2[idx] = __floats2half2_rn(v0, v1);
}

// ---------------- weight transform: wAh[br][tap][co][ci] fp16 ----------------
__global__ void wt_kernel(const float* __restrict__ w) {
    int idx = blockIdx.x * blockDim.x + threadIdx.x;
    if (idx >= NBR * 9 * COUT * CIN) return;
    int ci = idx % CIN; int t = idx / CIN;
    int co = t % COUT; t /= COUT;
    int tap = t % 9; int br = t / 9;
    g_wAh[idx] = __float2half_rn(w[(((size_t)br * COUT + co) * CIN + ci) * 9 + tap]);
}

// ---------------- xn ----------------
__global__ void xn_kernel(const float* __restrict__ x) {
    int idx = blockIdx.x * blockDim.x + threadIdx.x;
    if (idx >= NB * 4 * Hh * Ww) return;
    int hw = idx % (Hh * Ww);
    int t = idx / (Hh * Ww);
    int g = t % 4, bb = t / 4;
    const float* xp = x + ((size_t)bb * CIN + g * 32) * (Hh * Ww) + hw;
    float s = 0.f;
#pragma unroll
    for (int c = 0; c < 32; c++) { float v = xp[(size_t)c * Hh * Ww]; s += v * v; }
    g_xn[idx] = sqrtf(s);
}

// ---------------- fp16 mma.sync conv, cp.async double-buffered ----------------
// A smem: [128 co][40 halfs] (80B rows); B smem: half2 [16 kpair][136 px].
#define LDA2 40
#define NB2  136

struct ConvSmem {
    __align__(16) __half A[2][128 * LDA2];
    __align__(16) __half2 B[2][16 * NB2];
};

__device__ __forceinline__ void stage_tile(ConvSmem* S, int buf, int it, int tid,
                                           const __half* wbr, const __half2* yb2,
                                           int r, int d) {
    int tap = it >> 2, q = it & 3;
    int kh = tap / 3, kw = tap - kh * 3;
    // A: [128co][32ci] halfs -> rows of 40, 16B chunks
    const __half* wsrc = wbr + (size_t)tap * COUT * CIN + q * 32;
#pragma unroll
    for (int i = tid; i < 512; i += 256) {
        int co = i >> 2, k8 = i & 3;
        cpa16(&S->A[buf][co * LDA2 + k8 * 8], wsrc + (size_t)co * CIN + k8 * 8);
    }
    // B: 16 ci-pairs x 136 px half2, 4B chunks
    const __half2* ysrc = yb2 + (size_t)q * 16 * EXHW
                        + (size_t)(r + 21 + d * (kh - 1)) * EXW + (21 + d * (kw - 1));
    int kr = tid >> 4, c0 = tid & 15;
    const __half2* rowp = ysrc + (size_t)kr * EXHW;
    __half2* dstrow = &S->B[buf][kr * NB2];
#pragma unroll
    for (int c = c0; c < 136; c += 16) cpa4(dstrow + c, rowp + c);
}

__global__ __launch_bounds__(256, 2) void conv_mma_kernel(const float* __restrict__ bias) {
    __shared__ ConvSmem S;
    int tid = threadIdx.x, warp = tid >> 5, lane = tid & 31;
    int gq = lane >> 2, tig = lane & 3;
    int br = blockIdx.y >> 1, bb = blockIdx.y & 1;
    int r = blockIdx.x;
    int d = c_rad[br];
    int wm = warp & 3, wn = warp >> 2;
    int ntiles = wn ? 8 : 9;
    int tbase = wn * 9;

    const __half* wbr = g_wAh + (size_t)br * 9 * COUT * CIN;
    const __half2* yb2 = g_yext2 + (size_t)bb * 64 * EXHW;

    float acc[2][9][4];
#pragma unroll
    for (int mt = 0; mt < 2; mt++)
#pragma unroll
        for (int t = 0; t < 9; t++)
#pragma unroll
            for (int u = 0; u < 4; u++) acc[mt][t][u] = 0.f;

    stage_tile(&S, 0, 0, tid, wbr, yb2, r, d);
    CP_COMMIT();

    for (int it = 0; it < 36; ++it) {
        if (it < 35) {
            stage_tile(&S, (it + 1) & 1, it + 1, tid, wbr, yb2, r, d);
            CP_COMMIT();
            asm volatile("cp.async.wait_group 1;" ::: "memory");
        } else {
            asm volatile("cp.async.wait_group 0;" ::: "memory");
        }
        __syncthreads();
        const uint32_t* sA = (const uint32_t*)S.A[it & 1];   // half2 view, row = 20 h2
        const uint32_t* sB = (const uint32_t*)S.B[it & 1];
#pragma unroll
        for (int kk2 = 0; kk2 < 2; kk2++) {                  // two K=16 steps
            uint32_t a[2][4];
#pragma unroll
            for (int mt = 0; mt < 2; mt++) {
                int row = wm * 32 + mt * 16 + gq;
                int base = row * 20 + kk2 * 8 + tig;
                a[mt][0] = sA[base];
                a[mt][1] = sA[base + 8 * 20];
                a[mt][2] = sA[base + 4];
                a[mt][3] = sA[base + 8 * 20 + 4];
            }
            int kb = kk2 * 8 + tig;
#pragma unroll
            for (int t = 0; t < 9; t++) {
                if (t < ntiles) {
                    int col = (tbase + t) * 8 + gq;
                    uint32_t b0 = sB[kb * NB2 + col];
                    uint32_t b1 = sB[(kb + 4) * NB2 + col];
                    mma16(acc[0][t], a[0], b0, b1);
                    mma16(acc[1][t], a[1], b0, b1);
                }
            }
        }
        __syncthreads();
    }

    // epilogue: bias + store to g_yg (fp32)
    float* og = g_yg + (size_t)(br * NB + bb) * COUT * HP * WP + (size_t)r * WP;
#pragma unroll
    for (int mt = 0; mt < 2; mt++) {
        int co0 = wm * 32 + mt * 16 + gq, co1 = co0 + 8;
        float bv0 = bias[br * COUT + co0], bv1 = bias[br * COUT + co1];
#pragma unroll
        for (int t = 0; t < 9; t++) {
            if (t < ntiles) {
                int col = (tbase + t) * 8 + 2 * tig;
                *(float2*)&og[(size_t)co0 * HP * WP + col] =
                    make_float2(acc[mt][t][0] + bv0, acc[mt][t][1] + bv0);
                *(float2*)&og[(size_t)co1 * HP * WP + col] =
                    make_float2(acc[mt][t][2] + bv1, acc[mt][t][3] + bv1);
            }
        }
    }
}

// ---------------- yn ----------------
__global__ void yn_kernel() {
    int idx = blockIdx.x * blockDim.x + threadIdx.x;
    if (idx >= NBR * NB * 4 * HP * WP) return;
    int hw = idx % (HP * WP);
    int t = idx / (HP * WP);
    int g = t % 4; t /= 4;
    int bb = t % 2; int br = t / 2;
    const float* p = g_yg + ((size_t)(br * NB + bb) * COUT + g * 32) * HP * WP + hw;
    float s = 0.f;
#pragma unroll
    for (int c = 0; c < 32; c++) { float v = p[(size_t)c * HP * WP]; s += v * v; }
    g_yn[idx] = sqrtf(s);
}

// ---------------- 81-shift grouped correlation (float2 channel pairs) ----------------
__global__ __launch_bounds__(256, 2) void corr_kernel(const float* __restrict__ x,
                                                      float* __restrict__ out) {
    int bz = blockIdx.z;
    int br = bz % 6; int t2 = bz / 6;
    int g = t2 & 3; int bb = t2 >> 2;
    int hx0 = blockIdx.x * 16, hy0 = blockIdx.y * 16;
    int tx = threadIdx.x & 15, ty = threadIdx.x >> 4;

    __shared__ float2 syg2[4][24][25];
    __shared__ float2 sxg2[4][16][17];
    __shared__ float syn[24][25];

    const float* ygb = g_yg + ((size_t)(br * NB + bb) * COUT + g * 32) * HP * WP;
    const float* xgb = x + ((size_t)bb * CIN + g * 32) * Hh * Ww;

    float acc[81];
#pragma unroll
    for (int s = 0; s < 81; s++) acc[s] = 0.f;

    for (int cb = 0; cb < 32; cb += 8) {
        for (int idx = threadIdx.x; idx < 4 * 24 * 24; idx += 256) {
            int cp = idx / 576; int rem = idx - cp * 576;
            int rr = rem / 24; int cc = rem - rr * 24;
            const float* p = ygb + (size_t)(cb + 2 * cp) * HP * WP
                           + (size_t)(hy0 + rr) * WP + hx0 + cc;
            syg2[cp][rr][cc] = make_float2(p[0], p[HP * WP]);
        }
        for (int idx = threadIdx.x; idx < 4 * 16 * 16; idx += 256) {
            int cp = idx >> 8; int rem = idx & 255;
            int rr = rem >> 4; int cc = rem & 15;
            const float* p = xgb + (size_t)(cb + 2 * cp) * Hh * Ww
                           + (size_t)(hy0 + rr) * Ww + hx0 + cc;
            sxg2[cp][rr][cc] = make_float2(p[0], p[Hh * Ww]);
        }
        __syncthreads();
        float2 xr[4];
#pragma unroll
        for (int cp = 0; cp < 4; cp++) xr[cp] = sxg2[cp][ty][tx];
#pragma unroll
        for (int sx = 0; sx < 9; sx++) {
#pragma unroll
            for (int sy = 0; sy < 9; sy++) {
                float dsum = 0.f;
#pragma unroll
                for (int cp = 0; cp < 4; cp++) {
                    float2 yv = syg2[cp][ty + sx][tx + sy];
                    dsum += xr[cp].x * yv.x;
                    dsum += xr[cp].y * yv.y;
                }
                acc[sx * 9 + sy] += dsum;
            }
        }
        __syncthreads();
    }

    for (int idx = threadIdx.x; idx < 24 * 24; idx += 256) {
        int rr = idx / 24, cc = idx - rr * 24;
        syn[rr][cc] = g_yn[(((size_t)br * NB + bb) * 4 + g) * HP * WP
                           + (size_t)(hy0 + rr) * WP + hx0 + cc];
    }
    __syncthreads();

    float xnv = g_xn[((size_t)bb * 4 + g) * Hh * Ww + (size_t)(hy0 + ty) * Ww + hx0 + tx];
    size_t obase = ((size_t)(bb * 24 + br * 4 + g) * 81) * (Hh * Ww)
                 + (size_t)(hy0 + ty) * Ww + (hx0 + tx);
#pragma unroll
    for (int sx = 0; sx < 9; sx++) {
#pragma unroll
        for (int sy = 0; sy < 9; sy++) {
            float den = fmaxf(xnv * syn[ty + sx][tx + sy], 1e-8f);
            out[obase + (size_t)(sx * 9 + sy) * (Hh * Ww)] = acc[sx * 9 + sy] / den;
        }
    }
}

// ---------------- launch ----------------
extern "C" void kernel_launch(void* const* d_in, const int* in_sizes, int n_in,
                              void* d_out, int out_size) {
    const float* x    = (const float*)d_in[0];
    const float* y    = (const float*)d_in[1];
    const float* wts  = (const float*)d_in[2];
    const float* bias = (const float*)d_in[3];
    float* out = (float*)d_out;

    pad_kernel<<<(NB * 64 * EXHW + 255) / 256, 256>>>(y);
    wt_kernel<<<(NBR * 9 * COUT * CIN + 255) / 256, 256>>>(wts);
    xn_kernel<<<(NB * 4 * Hh * Ww + 255) / 256, 256>>>(x);
    conv_mma_kernel<<<dim3(104, 12), 256>>>(bias);
    yn_kernel<<<(NBR * NB * 4 * HP * WP + 255) / 256, 256>>>();
    corr_kernel<<<dim3(Ww / 16, Hh / 16, NB * 4 * NBR), 256>>>(x, out);
}

// round 6
// speedup vs baseline: 7.4784x; 1.2299x over previous
#include <cuda_runtime.h>
#include <cuda_fp16.h>
#include <math.h>
#include <cstdint>

#define Hh 96
#define Ww 128
#define HP 104
#define WP 136
#define CIN 128
#define COUT 128
#define NB 2
#define NBR 6
#define EXH 146            // HP + 2*21
#define EXW 178            // WP + 2*21
#define EXHW (EXH*EXW)

// -------- scratch (device globals: allocation-free) --------
__device__ __half g_ygh[(size_t)NBR * NB * HP * WP * 128];   // conv out, [br][bb][row][col][ch], 43.5MB
__device__ float g_yn[(size_t)NBR * NB * 4 * HP * WP];
__device__ float g_xn[(size_t)NB * 4 * Hh * Ww];
__device__ __half g_xh[(size_t)NB * Hh * Ww * 128];          // x fp16 [bb][row][col][ch]
__device__ __half2 g_yext2[(size_t)NB * 64 * EXHW];          // ci-pair interleaved fp16
__device__ __half g_wAh[(size_t)NBR * 9 * COUT * CIN];       // fp16 weights [br][tap][co][ci]

__constant__ int c_rad[6] = {1, 3, 5, 9, 13, 21};

__device__ __forceinline__ void mma16(float* c, const uint32_t* a, uint32_t b0, uint32_t b1) {
    asm volatile(
        "mma.sync.aligned.m16n8k16.row.col.f32.f16.f16.f32 "
        "{%0,%1,%2,%3}, {%4,%5,%6,%7}, {%8,%9}, {%0,%1,%2,%3};"
        : "+f"(c[0]), "+f"(c[1]), "+f"(c[2]), "+f"(c[3])
        : "r"(a[0]), "r"(a[1]), "r"(a[2]), "r"(a[3]), "r"(b0), "r"(b1));
}
__device__ __forceinline__ void cpa16(void* dst, const void* src) {
    uint32_t d = (uint32_t)__cvta_generic_to_shared(dst);
    asm volatile("cp.async.cg.shared.global [%0], [%1], 16;" :: "r"(d), "l"(src));
}
__device__ __forceinline__ void cpa4(void* dst, const void* src) {
    uint32_t d = (uint32_t)__cvta_generic_to_shared(dst);
    asm volatile("cp.async.ca.shared.global [%0], [%1], 4;" :: "r"(d), "l"(src));
}
#define CP_COMMIT() asm volatile("cp.async.commit_group;" ::: "memory")

// ---------------- y_ext fp16 half2 (ci pairs): reflect pad + 21 zero halo ----------------
__global__ void pad_kernel(const float* __restrict__ y) {
    int idx = blockIdx.x * blockDim.x + threadIdx.x;
    if (idx >= NB * 64 * EXHW) return;
    int c = idx % EXW; int t = idx / EXW;
    int rr = t % EXH; t /= EXH;
    int cp = t % 64; int bb = t / 64;
    int pr = rr - 21, pc = c - 21;
    float v0 = 0.f, v1 = 0.f;
    if (pr >= 0 && pr < HP && pc >= 0 && pc < WP) {
        int yr = pr - 4; yr = yr < 0 ? -yr : yr; yr = yr >= Hh ? 2 * Hh - 2 - yr : yr;
        int yc = pc - 4; yc = yc < 0 ? -yc : yc; yc = yc >= Ww ? 2 * Ww - 2 - yc : yc;
        const float* p = y + ((size_t)bb * CIN + 2 * cp) * (Hh * Ww) + (size_t)yr * Ww + yc;
        v0 = p[0]; v1 = p[Hh * Ww];
    }
    g_yext2[idx] = __floats2half2_rn(v0, v1);
}

// ---------------- weight transform: wAh[br][tap][co][ci] fp16 ----------------
__global__ void wt_kernel(const float* __restrict__ w) {
    int idx = blockIdx.x * blockDim.x + threadIdx.x;
    if (idx >= NBR * 9 * COUT * CIN) return;
    int ci = idx % CIN; int t = idx / CIN;
    int co = t % COUT; t /= COUT;
    int tap = t % 9; int br = t / 9;
    g_wAh[idx] = __float2half_rn(w[(((size_t)br * COUT + co) * CIN + ci) * 9 + tap]);
}

// ---------------- xn + x fp16 transpose ----------------
__global__ void xn_kernel(const float* __restrict__ x) {
    int idx = blockIdx.x * blockDim.x + threadIdx.x;
    if (idx >= NB * 4 * Hh * Ww) return;
    int hw = idx % (Hh * Ww);
    int t = idx / (Hh * Ww);
    int g = t % 4, bb = t / 4;
    const float* xp = x + ((size_t)bb * CIN + g * 32) * (Hh * Ww) + hw;
    __half* xo = g_xh + ((size_t)bb * Hh * Ww + hw) * 128 + g * 32;
    float s = 0.f;
#pragma unroll
    for (int c = 0; c < 32; c++) {
        float v = xp[(size_t)c * Hh * Ww];
        s += v * v;
        xo[c] = __float2half_rn(v);
    }
    g_xn[idx] = sqrtf(s);
}

// ---------------- fp16 mma.sync conv, cp.async double-buffered ----------------
#define LDA2 40
#define NB2  136

struct ConvSmem {
    union {
        struct {
            __align__(16) __half A[2][128 * LDA2];
            __align__(16) __half2 B[2][16 * NB2];
        } s;
        __align__(16) __half ep[136 * 128];
    };
};

__device__ __forceinline__ void stage_tile(ConvSmem* S, int buf, int it, int tid,
                                           const __half* wbr, const __half2* yb2,
                                           int r, int d) {
    int tap = it >> 2, q = it & 3;
    int kh = tap / 3, kw = tap - kh * 3;
    const __half* wsrc = wbr + (size_t)tap * COUT * CIN + q * 32;
#pragma unroll
    for (int i = tid; i < 512; i += 256) {
        int co = i >> 2, k8 = i & 3;
        cpa16(&S->s.A[buf][co * LDA2 + k8 * 8], wsrc + (size_t)co * CIN + k8 * 8);
    }
    const __half2* ysrc = yb2 + (size_t)q * 16 * EXHW
                        + (size_t)(r + 21 + d * (kh - 1)) * EXW + (21 + d * (kw - 1));
    int kr = tid >> 4, c0 = tid & 15;
    const __half2* rowp = ysrc + (size_t)kr * EXHW;
    __half2* dstrow = &S->s.B[buf][kr * NB2];
#pragma unroll
    for (int c = c0; c < 136; c += 16) cpa4(dstrow + c, rowp + c);
}

__global__ __launch_bounds__(256, 2) void conv_mma_kernel(const float* __restrict__ bias) {
    __shared__ ConvSmem S;
    int tid = threadIdx.x, warp = tid >> 5, lane = tid & 31;
    int gq = lane >> 2, tig = lane & 3;
    int br = blockIdx.y >> 1, bb = blockIdx.y & 1;
    int r = blockIdx.x;
    int d = c_rad[br];
    int wm = warp & 3, wn = warp >> 2;
    int ntiles = wn ? 8 : 9;
    int tbase = wn * 9;

    const __half* wbr = g_wAh + (size_t)br * 9 * COUT * CIN;
    const __half2* yb2 = g_yext2 + (size_t)bb * 64 * EXHW;

    float acc[2][9][4];
#pragma unroll
    for (int mt = 0; mt < 2; mt++)
#pragma unroll
        for (int t = 0; t < 9; t++)
#pragma unroll
            for (int u = 0; u < 4; u++) acc[mt][t][u] = 0.f;

    stage_tile(&S, 0, 0, tid, wbr, yb2, r, d);
    CP_COMMIT();

    for (int it = 0; it < 36; ++it) {
        if (it < 35) {
            stage_tile(&S, (it + 1) & 1, it + 1, tid, wbr, yb2, r, d);
            CP_COMMIT();
            asm volatile("cp.async.wait_group 1;" ::: "memory");
        } else {
            asm volatile("cp.async.wait_group 0;" ::: "memory");
        }
        __syncthreads();
        const uint32_t* sA = (const uint32_t*)S.s.A[it & 1];
        const uint32_t* sB = (const uint32_t*)S.s.B[it & 1];
#pragma unroll
        for (int kk2 = 0; kk2 < 2; kk2++) {
            uint32_t a[2][4];
#pragma unroll
            for (int mt = 0; mt < 2; mt++) {
                int row = wm * 32 + mt * 16 + gq;
                int base = row * 20 + kk2 * 8 + tig;
                a[mt][0] = sA[base];
                a[mt][1] = sA[base + 8 * 20];
                a[mt][2] = sA[base + 4];
                a[mt][3] = sA[base + 8 * 20 + 4];
            }
            int kb = kk2 * 8 + tig;
#pragma unroll
            for (int t = 0; t < 9; t++) {
                if (t < ntiles) {
                    int col = (tbase + t) * 8 + gq;
                    uint32_t b0 = sB[kb * NB2 + col];
                    uint32_t b1 = sB[(kb + 4) * NB2 + col];
                    mma16(acc[0][t], a[0], b0, b1);
                    mma16(acc[1][t], a[1], b0, b1);
                }
            }
        }
        __syncthreads();
    }

    // epilogue: bias + fp16 transpose -> g_ygh[row][col][ch]
#pragma unroll
    for (int mt = 0; mt < 2; mt++) {
        int co0 = wm * 32 + mt * 16 + gq, co1 = co0 + 8;
        float bv0 = bias[br * COUT + co0], bv1 = bias[br * COUT + co1];
#pragma unroll
        for (int t = 0; t < 9; t++) {
            if (t < ntiles) {
                int col = (tbase + t) * 8 + 2 * tig;
                S.ep[col * 128 + co0] = __float2half(acc[mt][t][0] + bv0);
                S.ep[(col + 1) * 128 + co0] = __float2half(acc[mt][t][1] + bv0);
                S.ep[col * 128 + co1] = __float2half(acc[mt][t][2] + bv1);
                S.ep[(col + 1) * 128 + co1] = __float2half(acc[mt][t][3] + bv1);
            }
        }
    }
    __syncthreads();
    __half* dst = g_ygh + ((size_t)(br * NB + bb) * HP + r) * WP * 128;
    const uint4* src = (const uint4*)S.ep;
    for (int i = tid; i < 136 * 128 / 8; i += 256)
        ((uint4*)dst)[i] = src[i];
}

// ---------------- yn from fp16 ----------------
__global__ void yn_kernel() {
    int idx = blockIdx.x * blockDim.x + threadIdx.x;
    if (idx >= NBR * NB * 4 * HP * WP) return;
    int hw = idx % (HP * WP);
    int t = idx / (HP * WP);
    int g = t % 4; t /= 4;
    int bb = t % 2; int br = t / 2;
    const __half2* p = (const __half2*)(g_ygh + ((size_t)(br * NB + bb) * HP * WP + hw) * 128 + g * 32);
    float s = 0.f;
#pragma unroll
    for (int c = 0; c < 16; c++) {
        float2 f = __half22float2(p[c]);
        s += f.x * f.x + f.y * f.y;
    }
    g_yn[idx] = sqrtf(s);
}

// ---------------- tensor-core 81-shift correlation ----------------
// CTA: one (bb,g,br,row). 8 warps = 8 x 16-px col tiles.
// Per sx: E[16x24] = X^T[16x32] * Y[32x24] via 6 mma; extract E[p][p+sy].
#define YLD 40   // halfs per col slot in Y stage (32 + 8 pad), 80B

__global__ __launch_bounds__(256, 3) void corr_kernel(float* __restrict__ out) {
    __shared__ __align__(16) __half Yb[2][136 * YLD];
    __shared__ float Es[8][16 * 25];

    int tid = threadIdx.x, warp = tid >> 5, lane = tid & 31;
    int gq = lane >> 2, tig = lane & 3;
    int r = blockIdx.x;
    int br = blockIdx.y;
    int zz = blockIdx.z;
    int bb = zz >> 2, g = zz & 3;
    int c0 = warp * 16;

    // A fragments: held in regs, reused across all 9 sx
    const __half* xb = g_xh + ((size_t)bb * Hh + r) * Ww * 128 + g * 32;
    uint32_t a[2][4];
#pragma unroll
    for (int ks = 0; ks < 2; ks++) {
        a[ks][0] = *(const uint32_t*)(xb + (size_t)(c0 + gq) * 128 + ks * 16 + 2 * tig);
        a[ks][1] = *(const uint32_t*)(xb + (size_t)(c0 + gq + 8) * 128 + ks * 16 + 2 * tig);
        a[ks][2] = *(const uint32_t*)(xb + (size_t)(c0 + gq) * 128 + ks * 16 + 8 + 2 * tig);
        a[ks][3] = *(const uint32_t*)(xb + (size_t)(c0 + gq + 8) * 128 + ks * 16 + 8 + 2 * tig);
    }

    const __half* ysrc = g_ygh + (size_t)(br * NB + bb) * HP * WP * 128 + g * 32;
    // stage row r (sx=0)
    {
        const __half* rowp = ysrc + (size_t)r * WP * 128;
        for (int i = tid; i < 544; i += 256) {
            int col = i >> 2, c = i & 3;
            cpa16(&Yb[0][col * YLD + c * 8], rowp + (size_t)col * 128 + c * 8);
        }
    }
    CP_COMMIT();

    const float* xnrow = g_xn + ((size_t)bb * 4 + g) * Hh * Ww + (size_t)r * Ww + c0;
    const float* ynb = g_yn + ((size_t)(br * NB + bb) * 4 + g) * HP * WP;
    size_t ob0 = ((size_t)(bb * 24 + br * 4 + g) * 81) * (Hh * Ww) + (size_t)r * Ww + c0;

    for (int sx = 0; sx < 9; sx++) {
        if (sx < 8) {
            const __half* rowp = ysrc + (size_t)(r + sx + 1) * WP * 128;
            __half* db = Yb[(sx + 1) & 1];
            for (int i = tid; i < 544; i += 256) {
                int col = i >> 2, c = i & 3;
                cpa16(&db[col * YLD + c * 8], rowp + (size_t)col * 128 + c * 8);
            }
            CP_COMMIT();
            asm volatile("cp.async.wait_group 1;" ::: "memory");
        } else {
            asm volatile("cp.async.wait_group 0;" ::: "memory");
        }
        __syncthreads();

        const uint32_t* sB = (const uint32_t*)Yb[sx & 1];   // half2 units, col stride 20
        float e[3][4];
#pragma unroll
        for (int nt = 0; nt < 3; nt++) {
            e[nt][0] = e[nt][1] = e[nt][2] = e[nt][3] = 0.f;
            int col = c0 + nt * 8 + gq;
#pragma unroll
            for (int ks = 0; ks < 2; ks++) {
                uint32_t b0 = sB[col * 20 + tig + 8 * ks];
                uint32_t b1 = sB[col * 20 + tig + 4 + 8 * ks];
                mma16(e[nt], a[ks], b0, b1);
            }
        }
        // dump E to warp-private smem
        float* Ew = Es[warp];
#pragma unroll
        for (int nt = 0; nt < 3; nt++) {
            int cc = nt * 8 + 2 * tig;
            Ew[gq * 25 + cc] = e[nt][0];
            Ew[gq * 25 + cc + 1] = e[nt][1];
            Ew[(gq + 8) * 25 + cc] = e[nt][2];
            Ew[(gq + 8) * 25 + cc + 1] = e[nt][3];
        }
        __syncwarp();
        // extract band, normalize, store
        const float* ynrow = ynb + (size_t)(r + sx) * WP + c0;
        size_t ob = ob0 + (size_t)sx * 9 * (Hh * Ww);
#pragma unroll
        for (int u = 0; u < 5; u++) {
            int idx = lane + u * 32;
            if (idx < 144) {
                int sy = idx >> 4, p = idx & 15;
                float num = Ew[p * 25 + p + sy];
                float den = fmaxf(xnrow[p] * ynrow[p + sy], 1e-8f);
                out[ob + (size_t)sy * (Hh * Ww) + p] = __fdividef(num, den);
            }
        }
        __syncthreads();
    }
}

// ---------------- launch ----------------
extern "C" void kernel_launch(void* const* d_in, const int* in_sizes, int n_in,
                              void* d_out, int out_size) {
    const float* x    = (const float*)d_in[0];
    const float* y    = (const float*)d_in[1];
    const float* wts  = (const float*)d_in[2];
    const float* bias = (const float*)d_in[3];
    float* out = (float*)d_out;

    pad_kernel<<<(NB * 64 * EXHW + 255) / 256, 256>>>(y);
    wt_kernel<<<(NBR * 9 * COUT * CIN + 255) / 256, 256>>>(wts);
    xn_kernel<<<(NB * 4 * Hh * Ww + 255) / 256, 256>>>(x);
    conv_mma_kernel<<<dim3(104, 12), 256>>>(bias);
    yn_kernel<<<(NBR * NB * 4 * HP * WP + 255) / 256, 256>>>();
    corr_kernel<<<dim3(Hh, NBR, NB * 4), 256>>>(out);
}

// round 9
// speedup vs baseline: 8.4715x; 1.1328x over previous
#include <cuda_runtime.h>
#include <cuda_fp16.h>
#include <math.h>
#include <cstdint>

#define Hh 96
#define Ww 128
#define HP 104
#define WP 136
#define CIN 128
#define COUT 128
#define NB 2
#define NBR 6
#define EXH 146            // HP + 2*21
#define EXW 178            // WP + 2*21
#define EXHW (EXH*EXW)

// -------- scratch (device globals: allocation-free) --------
__device__ __align__(16) __half g_ygh[(size_t)NBR * NB * HP * WP * 128];   // conv out [br][bb][row][col][ch]
__device__ __align__(16) float g_yn[(size_t)NBR * NB * 4 * HP * WP];
__device__ __align__(16) float g_xn[(size_t)NB * 4 * Hh * Ww];
__device__ __align__(16) __half g_xh[(size_t)NB * Hh * Ww * 128];          // x fp16 [bb][row][col][ch]
__device__ __align__(16) __half2 g_yext2[(size_t)NB * 64 * EXHW + 64];     // ci-pair fp16
__device__ __align__(16) __half g_wAh[(size_t)NBR * 9 * COUT * CIN];       // fp16 weights [br][tap][co][ci]

__constant__ int c_rad[6] = {1, 3, 5, 9, 13, 21};

__device__ __forceinline__ void mma16(float* c, const uint32_t* a, uint32_t b0, uint32_t b1) {
    asm volatile(
        "mma.sync.aligned.m16n8k16.row.col.f32.f16.f16.f32 "
        "{%0,%1,%2,%3}, {%4,%5,%6,%7}, {%8,%9}, {%0,%1,%2,%3};"
        : "+f"(c[0]), "+f"(c[1]), "+f"(c[2]), "+f"(c[3])
        : "r"(a[0]), "r"(a[1]), "r"(a[2]), "r"(a[3]), "r"(b0), "r"(b1));
}
__device__ __forceinline__ void ldsm_x4(uint32_t* r, uint32_t addr) {
    asm volatile("ldmatrix.sync.aligned.m8n8.x4.shared.b16 {%0,%1,%2,%3}, [%4];"
                 : "=r"(r[0]), "=r"(r[1]), "=r"(r[2]), "=r"(r[3]) : "r"(addr));
}
__device__ __forceinline__ void ldsm_x2(uint32_t* r, uint32_t addr) {
    asm volatile("ldmatrix.sync.aligned.m8n8.x2.shared.b16 {%0,%1}, [%2];"
                 : "=r"(r[0]), "=r"(r[1]) : "r"(addr));
}
__device__ __forceinline__ void cpa16(void* dst, const void* src) {
    uint32_t d = (uint32_t)__cvta_generic_to_shared(dst);
    asm volatile("cp.async.cg.shared.global [%0], [%1], 16;" :: "r"(d), "l"(src));
}
__device__ __forceinline__ void cpa4(void* dst, const void* src) {
    uint32_t d = (uint32_t)__cvta_generic_to_shared(dst);
    asm volatile("cp.async.ca.shared.global [%0], [%1], 4;" :: "r"(d), "l"(src));
}
#define CP_COMMIT() asm volatile("cp.async.commit_group;" ::: "memory")

// ---------------- y_ext fp16 half2 (ci pairs): reflect pad + 21 zero halo ----------------
__global__ void pad_kernel(const float* __restrict__ y) {
    int idx = blockIdx.x * blockDim.x + threadIdx.x;
    if (idx >= NB * 64 * EXHW) return;
    int c = idx % EXW; int t = idx / EXW;
    int rr = t % EXH; t /= EXH;
    int cp = t % 64; int bb = t / 64;
    int pr = rr - 21, pc = c - 21;
    float v0 = 0.f, v1 = 0.f;
    if (pr >= 0 && pr < HP && pc >= 0 && pc < WP) {
        int yr = pr - 4; yr = yr < 0 ? -yr : yr; yr = yr >= Hh ? 2 * Hh - 2 - yr : yr;
        int yc = pc - 4; yc = yc < 0 ? -yc : yc; yc = yc >= Ww ? 2 * Ww - 2 - yc : yc;
        const float* p = y + ((size_t)bb * CIN + 2 * cp) * (Hh * Ww) + (size_t)yr * Ww + yc;
        v0 = p[0]; v1 = p[Hh * Ww];
    }
    g_yext2[idx] = __floats2half2_rn(v0, v1);
}

// ---------------- weight transform: wAh[br][tap][co][ci] fp16 ----------------
__global__ void wt_kernel(const float* __restrict__ w) {
    int idx = blockIdx.x * blockDim.x + threadIdx.x;
    if (idx >= NBR * 9 * COUT * CIN) return;
    int ci = idx % CIN; int t = idx / CIN;
    int co = t % COUT; t /= COUT;
    int tap = t % 9; int br = t / 9;
    g_wAh[idx] = __float2half_rn(w[(((size_t)br * COUT + co) * CIN + ci) * 9 + tap]);
}

// ---------------- xn + x fp16 transpose ----------------
__global__ void xn_kernel(const float* __restrict__ x) {
    int idx = blockIdx.x * blockDim.x + threadIdx.x;
    if (idx >= NB * 4 * Hh * Ww) return;
    int hw = idx % (Hh * Ww);
    int t = idx / (Hh * Ww);
    int g = t % 4, bb = t / 4;
    const float* xp = x + ((size_t)bb * CIN + g * 32) * (Hh * Ww) + hw;
    __half* xo = g_xh + ((size_t)bb * Hh * Ww + hw) * 128 + g * 32;
    float s = 0.f;
#pragma unroll
    for (int c = 0; c < 32; c++) {
        float v = xp[(size_t)c * Hh * Ww];
        s += v * v;
        xo[c] = __float2half_rn(v);
    }
    g_xn[idx] = sqrtf(s);
}

// ---------------- fp16 mma.sync conv (ldmatrix fragment loads) ----------------
// A smem: [128 co][40 halfs] (80B rows). B smem: [136 col][20 half2] (80B slots,
// halves 0..31 of the k dimension in the first 16 half2 of each slot).
#define LDA2 40
#define BCOL 20

struct ConvSmem {
    union {
        struct {
            __align__(16) __half A[2][128 * LDA2];    // 20480 B
            __align__(16) __half2 Bt[2][136 * BCOL];  // 21760 B
        } s;
        __align__(16) __half ep[136 * 128];           // 34816 B
    };
};

__device__ __forceinline__ void stage_tile(ConvSmem* S, int buf, int it, int tid,
                                           const __half* wbr, const __half2* yb2,
                                           int r, int d) {
    int tap = it >> 2, q = it & 3;
    int kh = tap / 3, kw = tap - kh * 3;
    // A: [128co][32ci] halfs, 16B chunks
    const __half* wsrc = wbr + (size_t)tap * COUT * CIN + q * 32;
#pragma unroll
    for (int i = tid; i < 512; i += 256) {
        int co = i >> 2, k8 = i & 3;
        cpa16(&S->s.A[buf][co * LDA2 + k8 * 8], wsrc + (size_t)co * CIN + k8 * 8);
    }
    // B transposed: dst [col][kpair], src 16 ci-pair rows x 136 px, 4B chunks
    const __half2* ysrc = yb2 + (size_t)q * 16 * EXHW
                        + (size_t)(r + 21 + d * (kh - 1)) * EXW + (21 + d * (kw - 1));
    int kr = tid >> 4, c0 = tid & 15;
    const __half2* rowp = ysrc + (size_t)kr * EXHW;
    __half2* bt = S->s.Bt[buf];
#pragma unroll
    for (int c = c0; c < 136; c += 16) cpa4(&bt[c * BCOL + kr], rowp + c);
}

__global__ __launch_bounds__(256, 2) void conv_mma_kernel(const float* __restrict__ bias) {
    __shared__ ConvSmem S;
    int tid = threadIdx.x, warp = tid >> 5, lane = tid & 31;
    int gq = lane >> 2, tig = lane & 3;
    int br = blockIdx.y >> 1, bb = blockIdx.y & 1;
    int r = blockIdx.x;
    int d = c_rad[br];
    int wm = warp & 3, wn = warp >> 2;
    int ntiles = wn ? 8 : 9;
    int tbase = wn * 9;

    const __half* wbr = g_wAh + (size_t)br * 9 * COUT * CIN;
    const __half2* yb2 = g_yext2 + (size_t)bb * 64 * EXHW;

    // ldmatrix per-lane address components
    int aro = (lane & 15);              // rows 0..15 across matrices 0/1 (and 2/3)
    int ako = (lane >> 4) << 3;         // +8 halves for matrices 2/3
    int bco = (lane & 7) + ((lane >> 4) & 1) * 8;  // col within 2-tile window
    int bko = ((lane >> 3) & 1) * 4;    // +4 half2 (k+8) for matrices 1/3

    float acc[2][9][4];
#pragma unroll
    for (int mt = 0; mt < 2; mt++)
#pragma unroll
        for (int t = 0; t < 9; t++)
#pragma unroll
            for (int u = 0; u < 4; u++) acc[mt][t][u] = 0.f;

    stage_tile(&S, 0, 0, tid, wbr, yb2, r, d);
    CP_COMMIT();

    for (int it = 0; it < 36; ++it) {
        if (it < 35) {
            stage_tile(&S, (it + 1) & 1, it + 1, tid, wbr, yb2, r, d);
            CP_COMMIT();
            asm volatile("cp.async.wait_group 1;" ::: "memory");
        } else {
            asm volatile("cp.async.wait_group 0;" ::: "memory");
        }
        __syncthreads();

        uint32_t sAb = (uint32_t)__cvta_generic_to_shared(S.s.A[it & 1]);
        uint32_t sBb = (uint32_t)__cvta_generic_to_shared(S.s.Bt[it & 1]);
#pragma unroll
        for (int kk2 = 0; kk2 < 2; kk2++) {
            uint32_t a0[4], a1[4];
            ldsm_x4(a0, sAb + ((wm * 32 + aro) * LDA2 + kk2 * 16 + ako) * 2);
            ldsm_x4(a1, sAb + ((wm * 32 + 16 + aro) * LDA2 + kk2 * 16 + ako) * 2);
#pragma unroll
            for (int tp = 0; tp < 4; tp++) {
                uint32_t b[4];
                int colb = (tbase + 2 * tp) * 8 + bco;
                ldsm_x4(b, sBb + (colb * BCOL + kk2 * 8 + bko) * 4);
                mma16(acc[0][2 * tp], a0, b[0], b[1]);
                mma16(acc[1][2 * tp], a1, b[0], b[1]);
                mma16(acc[0][2 * tp + 1], a0, b[2], b[3]);
                mma16(acc[1][2 * tp + 1], a1, b[2], b[3]);
            }
            if (ntiles == 9) {
                uint32_t b[2];
                int colb = (tbase + 8) * 8 + bco;
                ldsm_x2(b, sBb + (colb * BCOL + kk2 * 8 + bko) * 4);
                mma16(acc[0][8], a0, b[0], b[1]);
                mma16(acc[1][8], a1, b[0], b[1]);
            }
        }
        __syncthreads();
    }

    // epilogue: bias + fp16 transpose -> g_ygh[row][col][ch]
#pragma unroll
    for (int mt = 0; mt < 2; mt++) {
        int co0 = wm * 32 + mt * 16 + gq, co1 = co0 + 8;
        float bv0 = bias[br * COUT + co0], bv1 = bias[br * COUT + co1];
#pragma unroll
        for (int t = 0; t < 9; t++) {
            if (t < ntiles) {
                int col = (tbase + t) * 8 + 2 * tig;
                S.ep[col * 128 + co0] = __float2half(acc[mt][t][0] + bv0);
                S.ep[(col + 1) * 128 + co0] = __float2half(acc[mt][t][1] + bv0);
                S.ep[col * 128 + co1] = __float2half(acc[mt][t][2] + bv1);
                S.ep[(col + 1) * 128 + co1] = __float2half(acc[mt][t][3] + bv1);
            }
        }
    }
    __syncthreads();
    __half* dst = g_ygh + ((size_t)(br * NB + bb) * HP + r) * WP * 128;
    const uint4* src = (const uint4*)S.ep;
    for (int i = tid; i < 136 * 128 / 8; i += 256)
        ((uint4*)dst)[i] = src[i];
}

// ---------------- yn from fp16 ----------------
__global__ void yn_kernel() {
    int idx = blockIdx.x * blockDim.x + threadIdx.x;
    if (idx >= NBR * NB * 4 * HP * WP) return;
    int hw = idx % (HP * WP);
    int t = idx / (HP * WP);
    int g = t % 4; t /= 4;
    int bb = t % 2; int br = t / 2;
    const __half2* p = (const __half2*)(g_ygh + ((size_t)(br * NB + bb) * HP * WP + hw) * 128 + g * 32);
    float s = 0.f;
#pragma unroll
    for (int c = 0; c < 16; c++) {
        float2 f = __half22float2(p[c]);
        s += f.x * f.x + f.y * f.y;
    }
    g_yn[idx] = sqrtf(s);
}

// ---------------- tensor-core 81-shift correlation ----------------
#define YLD 40

__global__ __launch_bounds__(256, 3) void corr_kernel(float* __restrict__ out) {
    __shared__ __align__(16) __half Yb[2][136 * YLD];
    __shared__ float Es[8][16 * 25];

    int tid = threadIdx.x, warp = tid >> 5, lane = tid & 31;
    int gq = lane >> 2, tig = lane & 3;
    int r = blockIdx.x;
    int br = blockIdx.y;
    int zz = blockIdx.z;
    int bb = zz >> 2, g = zz & 3;
    int c0 = warp * 16;

    const __half* xb = g_xh + ((size_t)bb * Hh + r) * Ww * 128 + g * 32;
    uint32_t a[2][4];
#pragma unroll
    for (int ks = 0; ks < 2; ks++) {
        a[ks][0] = *(const uint32_t*)(xb + (size_t)(c0 + gq) * 128 + ks * 16 + 2 * tig);
        a[ks][1] = *(const uint32_t*)(xb + (size_t)(c0 + gq + 8) * 128 + ks * 16 + 2 * tig);
        a[ks][2] = *(const uint32_t*)(xb + (size_t)(c0 + gq) * 128 + ks * 16 + 8 + 2 * tig);
        a[ks][3] = *(const uint32_t*)(xb + (size_t)(c0 + gq + 8) * 128 + ks * 16 + 8 + 2 * tig);
    }

    const __half* ysrc = g_ygh + (size_t)(br * NB + bb) * HP * WP * 128 + g * 32;
    {
        const __half* rowp = ysrc + (size_t)r * WP * 128;
        for (int i = tid; i < 544; i += 256) {
            int col = i >> 2, c = i & 3;
            cpa16(&Yb[0][col * YLD + c * 8], rowp + (size_t)col * 128 + c * 8);
        }
    }
    CP_COMMIT();

    const float* xnrow = g_xn + ((size_t)bb * 4 + g) * Hh * Ww + (size_t)r * Ww + c0;
    const float* ynb = g_yn + ((size_t)(br * NB + bb) * 4 + g) * HP * WP;
    size_t ob0 = ((size_t)(bb * 24 + br * 4 + g) * 81) * (Hh * Ww) + (size_t)r * Ww + c0;

    for (int sx = 0; sx < 9; sx++) {
        if (sx < 8) {
            const __half* rowp = ysrc + (size_t)(r + sx + 1) * WP * 128;
            __half* db = Yb[(sx + 1) & 1];
            for (int i = tid; i < 544; i += 256) {
                int col = i >> 2, c = i & 3;
                cpa16(&db[col * YLD + c * 8], rowp + (size_t)col * 128 + c * 8);
            }
            CP_COMMIT();
            asm volatile("cp.async.wait_group 1;" ::: "memory");
        } else {
            asm volatile("cp.async.wait_group 0;" ::: "memory");
        }
        __syncthreads();

        const uint32_t* sB = (const uint32_t*)Yb[sx & 1];
        float e[3][4];
#pragma unroll
        for (int nt = 0; nt < 3; nt++) {
            e[nt][0] = e[nt][1] = e[nt][2] = e[nt][3] = 0.f;
            int col = c0 + nt * 8 + gq;
#pragma unroll
            for (int ks = 0; ks < 2; ks++) {
                uint32_t b0 = sB[col * 20 + tig + 8 * ks];
                uint32_t b1 = sB[col * 20 + tig + 4 + 8 * ks];
                mma16(e[nt], a[ks], b0, b1);
            }
        }
        float* Ew = Es[warp];
#pragma unroll
        for (int nt = 0; nt < 3; nt++) {
            int cc = nt * 8 + 2 * tig;
            Ew[gq * 25 + cc] = e[nt][0];
            Ew[gq * 25 + cc + 1] = e[nt][1];
            Ew[(gq + 8) * 25 + cc] = e[nt][2];
            Ew[(gq + 8) * 25 + cc + 1] = e[nt][3];
        }
        __syncwarp();
        const float* ynrow = ynb + (size_t)(r + sx) * WP + c0;
        size_t ob = ob0 + (size_t)sx * 9 * (Hh * Ww);
#pragma unroll
        for (int u = 0; u < 5; u++) {
            int idx = lane + u * 32;
            if (idx < 144) {
                int sy = idx >> 4, p = idx & 15;
                float num = Ew[p * 25 + p + sy];
                float den = fmaxf(xnrow[p] * ynrow[p + sy], 1e-8f);
                out[ob + (size_t)sy * (Hh * Ww) + p] = __fdividef(num, den);
            }
        }
        __syncthreads();
    }
}

// ---------------- launch ----------------
extern "C" void kernel_launch(void* const* d_in, const int* in_sizes, int n_in,
                              void* d_out, int out_size) {
    const float* x    = (const float*)d_in[0];
    const float* y    = (const float*)d_in[1];
    const float* wts  = (const float*)d_in[2];
    const float* bias = (const float*)d_in[3];
    float* out = (float*)d_out;

    pad_kernel<<<(NB * 64 * EXHW + 255) / 256, 256>>>(y);
    wt_kernel<<<(NBR * 9 * COUT * CIN + 255) / 256, 256>>>(wts);
    xn_kernel<<<(NB * 4 * Hh * Ww + 255) / 256, 256>>>(x);
    conv_mma_kernel<<<dim3(104, 12), 256>>>(bias);
    yn_kernel<<<(NBR * NB * 4 * HP * WP + 255) / 256, 256>>>();
    corr_kernel<<<dim3(Hh, NBR, NB * 4), 256>>>(out);
}

// round 10
// speedup vs baseline: 8.7072x; 1.0278x over previous
#include <cuda_runtime.h>
#include <cuda_fp16.h>
#include <math.h>
#include <cstdint>

#define Hh 96
#define Ww 128
#define HP 104
#define WP 136
#define CIN 128
#define COUT 128
#define NB 2
#define NBR 6
#define EXH 146            // HP + 2*21
#define EXW 178            // WP + 2*21
#define EXHW (EXH*EXW)

// -------- scratch (device globals: allocation-free) --------
__device__ __align__(16) __half g_ygh[(size_t)NBR * NB * HP * WP * 128];   // conv out [br][bb][row][col][ch]
__device__ __align__(16) float g_yn[(size_t)NBR * NB * 4 * HP * WP];
__device__ __align__(16) float g_xn[(size_t)NB * 4 * Hh * Ww];
__device__ __align__(16) __half g_xh[(size_t)NB * Hh * Ww * 128];          // x fp16 [bb][row][col][ch]
__device__ __align__(16) __half2 g_yext2[(size_t)NB * 64 * EXHW + 64];     // ci-pair fp16
__device__ __align__(16) __half g_wAh[(size_t)NBR * 9 * COUT * CIN];       // fp16 weights [br][tap][co][ci]

__constant__ int c_rad[6] = {1, 3, 5, 9, 13, 21};

__device__ __forceinline__ void mma16(float* c, const uint32_t* a, uint32_t b0, uint32_t b1) {
    asm volatile(
        "mma.sync.aligned.m16n8k16.row.col.f32.f16.f16.f32 "
        "{%0,%1,%2,%3}, {%4,%5,%6,%7}, {%8,%9}, {%0,%1,%2,%3};"
        : "+f"(c[0]), "+f"(c[1]), "+f"(c[2]), "+f"(c[3])
        : "r"(a[0]), "r"(a[1]), "r"(a[2]), "r"(a[3]), "r"(b0), "r"(b1));
}
__device__ __forceinline__ void ldsm_x4(uint32_t* r, uint32_t addr) {
    asm volatile("ldmatrix.sync.aligned.m8n8.x4.shared.b16 {%0,%1,%2,%3}, [%4];"
                 : "=r"(r[0]), "=r"(r[1]), "=r"(r[2]), "=r"(r[3]) : "r"(addr));
}
__device__ __forceinline__ void ldsm_x2(uint32_t* r, uint32_t addr) {
    asm volatile("ldmatrix.sync.aligned.m8n8.x2.shared.b16 {%0,%1}, [%2];"
                 : "=r"(r[0]), "=r"(r[1]) : "r"(addr));
}
__device__ __forceinline__ void cpa16(void* dst, const void* src) {
    uint32_t d = (uint32_t)__cvta_generic_to_shared(dst);
    asm volatile("cp.async.cg.shared.global [%0], [%1], 16;" :: "r"(d), "l"(src));
}
__device__ __forceinline__ void cpa4(void* dst, const void* src) {
    uint32_t d = (uint32_t)__cvta_generic_to_shared(dst);
    asm volatile("cp.async.ca.shared.global [%0], [%1], 4;" :: "r"(d), "l"(src));
}
#define CP_COMMIT() asm volatile("cp.async.commit_group;" ::: "memory")

// ---------------- y_ext fp16 half2 (ci pairs): reflect pad + 21 zero halo ----------------
__global__ void pad_kernel(const float* __restrict__ y) {
    int idx = blockIdx.x * blockDim.x + threadIdx.x;
    if (idx >= NB * 64 * EXHW) return;
    int c = idx % EXW; int t = idx / EXW;
    int rr = t % EXH; t /= EXH;
    int cp = t % 64; int bb = t / 64;
    int pr = rr - 21, pc = c - 21;
    float v0 = 0.f, v1 = 0.f;
    if (pr >= 0 && pr < HP && pc >= 0 && pc < WP) {
        int yr = pr - 4; yr = yr < 0 ? -yr : yr; yr = yr >= Hh ? 2 * Hh - 2 - yr : yr;
        int yc = pc - 4; yc = yc < 0 ? -yc : yc; yc = yc >= Ww ? 2 * Ww - 2 - yc : yc;
        const float* p = y + ((size_t)bb * CIN + 2 * cp) * (Hh * Ww) + (size_t)yr * Ww + yc;
        v0 = p[0]; v1 = p[Hh * Ww];
    }
    g_yext2[idx] = __floats2half2_rn(v0, v1);
}

// ---------------- weight transform: wAh[br][tap][co][ci] fp16 ----------------
__global__ void wt_kernel(const float* __restrict__ w) {
    int idx = blockIdx.x * blockDim.x + threadIdx.x;
    if (idx >= NBR * 9 * COUT * CIN) return;
    int ci = idx % CIN; int t = idx / CIN;
    int co = t % COUT; t /= COUT;
    int tap = t % 9; int br = t / 9;
    g_wAh[idx] = __float2half_rn(w[(((size_t)br * COUT + co) * CIN + ci) * 9 + tap]);
}

// ---------------- xn + x fp16 transpose ----------------
__global__ void xn_kernel(const float* __restrict__ x) {
    int idx = blockIdx.x * blockDim.x + threadIdx.x;
    if (idx >= NB * 4 * Hh * Ww) return;
    int hw = idx % (Hh * Ww);
    int t = idx / (Hh * Ww);
    int g = t % 4, bb = t / 4;
    const float* xp = x + ((size_t)bb * CIN + g * 32) * (Hh * Ww) + hw;
    __half* xo = g_xh + ((size_t)bb * Hh * Ww + hw) * 128 + g * 32;
    float s = 0.f;
#pragma unroll
    for (int c = 0; c < 32; c++) {
        float v = xp[(size_t)c * Hh * Ww];
        s += v * v;
        xo[c] = __float2half_rn(v);
    }
    g_xn[idx] = sqrtf(s);
}

// ---------------- fp16 mma.sync conv ----------------
// it = q*9 + tap (tap = kh*3+kw). B staged once per (q,kh) = full EXW row,
// transposed [col][kpair]; kw handled as a column offset into the staged row.
#define LDA2 40
#define BCOL 20
#define A_HALFS 5120                 // 128*40
#define B_H2 3560                    // 178*20
#define OFF_B 20480                  // bytes: 2 A stages
#define CONV_SMEM (20480 + 2 * (B_H2 * 4))   // 48960 B

__device__ __forceinline__ void stage_A(__half* Abase, int it, int tid, const __half* wbr) {
    int q = it / 9, tap = it % 9;
    const __half* wsrc = wbr + (size_t)tap * COUT * CIN + q * 32;
#pragma unroll
    for (int i = tid; i < 512; i += 256) {
        int co = i >> 2, k8 = i & 3;
        cpa16(Abase + co * LDA2 + k8 * 8, wsrc + (size_t)co * CIN + k8 * 8);
    }
}

// stage piece of B stage s = q*3+kh: rows = ci-pairs q*16..+15, full EXW cols
__device__ __forceinline__ void stage_B(__half2* bt, int s, int piece, int tid,
                                        const __half2* yb2, int r, int d) {
    int q = s / 3, kh = s % 3;
    const __half2* rowbase = yb2 + (size_t)q * 16 * EXHW + (size_t)(r + 21 + d * (kh - 1)) * EXW;
    int lo = piece * 960, hi = (piece == 2) ? 2848 : lo + 960;
    for (int i = lo + tid; i < hi; i += 256) {
        int kr = i / 178, c = i - kr * 178;
        cpa4(bt + c * BCOL + kr, rowbase + (size_t)kr * EXHW + c);
    }
}

__global__ __launch_bounds__(256, 2) void conv_mma_kernel(const float* __restrict__ bias) {
    extern __shared__ __align__(16) char dsm[];
    __half* Asm = (__half*)dsm;
    __half2* Bsm = (__half2*)(dsm + OFF_B);
    __half* ep = (__half*)dsm;     // epilogue reuse

    int tid = threadIdx.x, warp = tid >> 5, lane = tid & 31;
    int gq = lane >> 2, tig = lane & 3;
    int br = blockIdx.y >> 1, bb = blockIdx.y & 1;
    int r = blockIdx.x;
    int d = c_rad[br];
    int wm = warp & 3, wn = warp >> 2;
    int ntiles = wn ? 8 : 9;
    int tbase = wn * 9;

    const __half* wbr = g_wAh + (size_t)br * 9 * COUT * CIN;
    const __half2* yb2 = g_yext2 + (size_t)bb * 64 * EXHW;

    // ldmatrix per-lane address components
    int aro = (lane & 15);
    int ako = (lane >> 4) << 3;
    int bco = (lane & 7) + ((lane >> 4) & 1) * 8;
    int bko = ((lane >> 3) & 1) * 4;

    float acc[2][9][4];
#pragma unroll
    for (int mt = 0; mt < 2; mt++)
#pragma unroll
        for (int t = 0; t < 9; t++)
#pragma unroll
            for (int u = 0; u < 4; u++) acc[mt][t][u] = 0.f;

    // prestage: full B stage 0, then A0  (groups 0, 1)
    stage_B(Bsm, 0, 0, tid, yb2, r, d);
    stage_B(Bsm, 0, 1, tid, yb2, r, d);
    stage_B(Bsm, 0, 2, tid, yb2, r, d);
    CP_COMMIT();
    stage_A(Asm, 0, tid, wbr);
    CP_COMMIT();

    for (int it = 0; it < 36; ++it) {
        int s = it / 3, p = it % 3;
        int kw = p;
        // prefetch piece p of B stage s+1 (group 2+2it)
        if (s + 1 < 12) stage_B(Bsm + ((s + 1) & 1) * B_H2, s + 1, p, tid, yb2, r, d);
        CP_COMMIT();
        // prefetch A for it+1 (group 3+2it)
        if (it + 1 < 36) stage_A(Asm + ((it + 1) & 1) * A_HALFS, it + 1, tid, wbr);
        CP_COMMIT();
        asm volatile("cp.async.wait_group 2;" ::: "memory");
        __syncthreads();

        uint32_t sAb = (uint32_t)__cvta_generic_to_shared(Asm + (it & 1) * A_HALFS);
        uint32_t sBb = (uint32_t)__cvta_generic_to_shared(Bsm + (s & 1) * B_H2);
        int off = 21 + d * (kw - 1);          // column offset into staged row
#pragma unroll
        for (int kk2 = 0; kk2 < 2; kk2++) {
            uint32_t a0[4], a1[4];
            ldsm_x4(a0, sAb + ((wm * 32 + aro) * LDA2 + kk2 * 16 + ako) * 2);
            ldsm_x4(a1, sAb + ((wm * 32 + 16 + aro) * LDA2 + kk2 * 16 + ako) * 2);
#pragma unroll
            for (int tp = 0; tp < 4; tp++) {
                uint32_t b[4];
                int colb = off + (tbase + 2 * tp) * 8 + bco;
                ldsm_x4(b, sBb + (colb * BCOL + kk2 * 8 + bko) * 4);
                mma16(acc[0][2 * tp], a0, b[0], b[1]);
                mma16(acc[1][2 * tp], a1, b[0], b[1]);
                mma16(acc[0][2 * tp + 1], a0, b[2], b[3]);
                mma16(acc[1][2 * tp + 1], a1, b[2], b[3]);
            }
            if (ntiles == 9) {
                uint32_t b[2];
                int colb = off + (tbase + 8) * 8 + bco;
                ldsm_x2(b, sBb + (colb * BCOL + kk2 * 8 + bko) * 4);
                mma16(acc[0][8], a0, b[0], b[1]);
                mma16(acc[1][8], a1, b[0], b[1]);
            }
        }
        __syncthreads();
    }
    asm volatile("cp.async.wait_group 0;" ::: "memory");
    __syncthreads();

    // epilogue: bias + fp16 transpose -> g_ygh[row][col][ch]
#pragma unroll
    for (int mt = 0; mt < 2; mt++) {
        int co0 = wm * 32 + mt * 16 + gq, co1 = co0 + 8;
        float bv0 = bias[br * COUT + co0], bv1 = bias[br * COUT + co1];
#pragma unroll
        for (int t = 0; t < 9; t++) {
            if (t < ntiles) {
                int col = (tbase + t) * 8 + 2 * tig;
                ep[col * 128 + co0] = __float2half(acc[mt][t][0] + bv0);
                ep[(col + 1) * 128 + co0] = __float2half(acc[mt][t][1] + bv0);
                ep[col * 128 + co1] = __float2half(acc[mt][t][2] + bv1);
                ep[(col + 1) * 128 + co1] = __float2half(acc[mt][t][3] + bv1);
            }
        }
    }
    __syncthreads();
    __half* dst = g_ygh + ((size_t)(br * NB + bb) * HP + r) * WP * 128;
    const uint4* src = (const uint4*)ep;
    for (int i = tid; i < 136 * 128 / 8; i += 256)
        ((uint4*)dst)[i] = src[i];
}

// ---------------- yn from fp16 ----------------
__global__ void yn_kernel() {
    int idx = blockIdx.x * blockDim.x + threadIdx.x;
    if (idx >= NBR * NB * 4 * HP * WP) return;
    int hw = idx % (HP * WP);
    int t = idx / (HP * WP);
    int g = t % 4; t /= 4;
    int bb = t % 2; int br = t / 2;
    const __half2* p = (const __half2*)(g_ygh + ((size_t)(br * NB + bb) * HP * WP + hw) * 128 + g * 32);
    float s = 0.f;
#pragma unroll
    for (int c = 0; c < 16; c++) {
        float2 f = __half22float2(p[c]);
        s += f.x * f.x + f.y * f.y;
    }
    g_yn[idx] = sqrtf(s);
}

// ---------------- tensor-core 81-shift correlation ----------------
#define YLD 40

__global__ __launch_bounds__(256, 3) void corr_kernel(float* __restrict__ out) {
    __shared__ __align__(16) __half Yb[2][136 * YLD];
    __shared__ float Es[8][16 * 25];

    int tid = threadIdx.x, warp = tid >> 5, lane = tid & 31;
    int gq = lane >> 2, tig = lane & 3;
    int r = blockIdx.x;
    int br = blockIdx.y;
    int zz = blockIdx.z;
    int bb = zz >> 2, g = zz & 3;
    int c0 = warp * 16;

    const __half* xb = g_xh + ((size_t)bb * Hh + r) * Ww * 128 + g * 32;
    uint32_t a[2][4];
#pragma unroll
    for (int ks = 0; ks < 2; ks++) {
        a[ks][0] = *(const uint32_t*)(xb + (size_t)(c0 + gq) * 128 + ks * 16 + 2 * tig);
        a[ks][1] = *(const uint32_t*)(xb + (size_t)(c0 + gq + 8) * 128 + ks * 16 + 2 * tig);
        a[ks][2] = *(const uint32_t*)(xb + (size_t)(c0 + gq) * 128 + ks * 16 + 8 + 2 * tig);
        a[ks][3] = *(const uint32_t*)(xb + (size_t)(c0 + gq + 8) * 128 + ks * 16 + 8 + 2 * tig);
    }

    const __half* ysrc = g_ygh + (size_t)(br * NB + bb) * HP * WP * 128 + g * 32;
    {
        const __half* rowp = ysrc + (size_t)r * WP * 128;
        for (int i = tid; i < 544; i += 256) {
            int col = i >> 2, c = i & 3;
            cpa16(&Yb[0][col * YLD + c * 8], rowp + (size_t)col * 128 + c * 8);
        }
    }
    CP_COMMIT();

    const float* xnrow = g_xn + ((size_t)bb * 4 + g) * Hh * Ww + (size_t)r * Ww + c0;
    const float* ynb = g_yn + ((size_t)(br * NB + bb) * 4 + g) * HP * WP;
    size_t ob0 = ((size_t)(bb * 24 + br * 4 + g) * 81) * (Hh * Ww) + (size_t)r * Ww + c0;

    for (int sx = 0; sx < 9; sx++) {
        if (sx < 8) {
            const __half* rowp = ysrc + (size_t)(r + sx + 1) * WP * 128;
            __half* db = Yb[(sx + 1) & 1];
            for (int i = tid; i < 544; i += 256) {
                int col = i >> 2, c = i & 3;
                cpa16(&db[col * YLD + c * 8], rowp + (size_t)col * 128 + c * 8);
            }
            CP_COMMIT();
            asm volatile("cp.async.wait_group 1;" ::: "memory");
        } else {
            asm volatile("cp.async.wait_group 0;" ::: "memory");
        }
        __syncthreads();

        const uint32_t* sB = (const uint32_t*)Yb[sx & 1];
        float e[3][4];
#pragma unroll
        for (int nt = 0; nt < 3; nt++) {
            e[nt][0] = e[nt][1] = e[nt][2] = e[nt][3] = 0.f;
            int col = c0 + nt * 8 + gq;
#pragma unroll
            for (int ks = 0; ks < 2; ks++) {
                uint32_t b0 = sB[col * 20 + tig + 8 * ks];
                uint32_t b1 = sB[col * 20 + tig + 4 + 8 * ks];
                mma16(e[nt], a[ks], b0, b1);
            }
        }
        float* Ew = Es[warp];
#pragma unroll
        for (int nt = 0; nt < 3; nt++) {
            int cc = nt * 8 + 2 * tig;
            Ew[gq * 25 + cc] = e[nt][0];
            Ew[gq * 25 + cc + 1] = e[nt][1];
            Ew[(gq + 8) * 25 + cc] = e[nt][2];
            Ew[(gq + 8) * 25 + cc + 1] = e[nt][3];
        }
        __syncwarp();
        const float* ynrow = ynb + (size_t)(r + sx) * WP + c0;
        size_t ob = ob0 + (size_t)sx * 9 * (Hh * Ww);
#pragma unroll
        for (int u = 0; u < 5; u++) {
            int idx = lane + u * 32;
            if (idx < 144) {
                int sy = idx >> 4, p = idx & 15;
                float num = Ew[p * 25 + p + sy];
                float den = fmaxf(xnrow[p] * ynrow[p + sy], 1e-8f);
                out[ob + (size_t)sy * (Hh * Ww) + p] = __fdividef(num, den);
            }
        }
        __syncthreads();
    }
}

// ---------------- launch ----------------
extern "C" void kernel_launch(void* const* d_in, const int* in_sizes, int n_in,
                              void* d_out, int out_size) {
    const float* x    = (const float*)d_in[0];
    const float* y    = (const float*)d_in[1];
    const float* wts  = (const float*)d_in[2];
    const float* bias = (const float*)d_in[3];
    float* out = (float*)d_out;

    pad_kernel<<<(NB * 64 * EXHW + 255) / 256, 256>>>(y);
    wt_kernel<<<(NBR * 9 * COUT * CIN + 255) / 256, 256>>>(wts);
    xn_kernel<<<(NB * 4 * Hh * Ww + 255) / 256, 256>>>(x);
    conv_mma_kernel<<<dim3(104, 12), 256, CONV_SMEM>>>(bias);
    yn_kernel<<<(NBR * NB * 4 * HP * WP + 255) / 256, 256>>>();
    corr_kernel<<<dim3(Hh, NBR, NB * 4), 256>>>(out);
}

// round 11
// speedup vs baseline: 9.2728x; 1.0650x over previous
#include <cuda_runtime.h>
#include <cuda_fp16.h>
#include <math.h>
#include <cstdint>

#define Hh 96
#define Ww 128
#define HP 104
#define WP 136
#define CIN 128
#define COUT 128
#define NB 2
#define NBR 6
#define EXH 146            // HP + 2*21
#define EXW 178            // WP + 2*21
#define EXHW (EXH*EXW)

// -------- scratch (device globals: allocation-free) --------
__device__ __align__(16) __half g_ygh[(size_t)NBR * NB * HP * WP * 128];   // conv out [br][bb][row][col][ch]
__device__ __align__(16) float g_yn[(size_t)NBR * NB * 4 * HP * WP];
__device__ __align__(16) float g_xn[(size_t)NB * 4 * Hh * Ww];
__device__ __align__(16) __half g_xh[(size_t)NB * Hh * Ww * 128];          // x fp16 [bb][row][col][ch]
__device__ __align__(16) __half2 g_yext2[(size_t)NB * 64 * EXHW + 64];     // ci-pair fp16
__device__ __align__(16) __half g_wAh[(size_t)NBR * 9 * COUT * CIN];       // fp16 weights [br][tap][co][ci]

__constant__ int c_rad[6] = {1, 3, 5, 9, 13, 21};

__device__ __forceinline__ void mma16(float* c, const uint32_t* a, uint32_t b0, uint32_t b1) {
    asm volatile(
        "mma.sync.aligned.m16n8k16.row.col.f32.f16.f16.f32 "
        "{%0,%1,%2,%3}, {%4,%5,%6,%7}, {%8,%9}, {%0,%1,%2,%3};"
        : "+f"(c[0]), "+f"(c[1]), "+f"(c[2]), "+f"(c[3])
        : "r"(a[0]), "r"(a[1]), "r"(a[2]), "r"(a[3]), "r"(b0), "r"(b1));
}
__device__ __forceinline__ void ldsm_x4(uint32_t* r, uint32_t addr) {
    asm volatile("ldmatrix.sync.aligned.m8n8.x4.shared.b16 {%0,%1,%2,%3}, [%4];"
                 : "=r"(r[0]), "=r"(r[1]), "=r"(r[2]), "=r"(r[3]) : "r"(addr));
}
__device__ __forceinline__ void ldsm_x2(uint32_t* r, uint32_t addr) {
    asm volatile("ldmatrix.sync.aligned.m8n8.x2.shared.b16 {%0,%1}, [%2];"
                 : "=r"(r[0]), "=r"(r[1]) : "r"(addr));
}
__device__ __forceinline__ void cpa16(void* dst, const void* src) {
    uint32_t d = (uint32_t)__cvta_generic_to_shared(dst);
    asm volatile("cp.async.cg.shared.global [%0], [%1], 16;" :: "r"(d), "l"(src));
}
__device__ __forceinline__ void cpa4(void* dst, const void* src) {
    uint32_t d = (uint32_t)__cvta_generic_to_shared(dst);
    asm volatile("cp.async.ca.shared.global [%0], [%1], 4;" :: "r"(d), "l"(src));
}
#define CP_COMMIT() asm volatile("cp.async.commit_group;" ::: "memory")

// ---------------- y_ext fp16 half2 (ci pairs): reflect pad + 21 zero halo ----------------
__global__ void pad_kernel(const float* __restrict__ y) {
    int idx = blockIdx.x * blockDim.x + threadIdx.x;
    if (idx >= NB * 64 * EXHW) return;
    int c = idx % EXW; int t = idx / EXW;
    int rr = t % EXH; t /= EXH;
    int cp = t % 64; int bb = t / 64;
    int pr = rr - 21, pc = c - 21;
    float v0 = 0.f, v1 = 0.f;
    if (pr >= 0 && pr < HP && pc >= 0 && pc < WP) {
        int yr = pr - 4; yr = yr < 0 ? -yr : yr; yr = yr >= Hh ? 2 * Hh - 2 - yr : yr;
        int yc = pc - 4; yc = yc < 0 ? -yc : yc; yc = yc >= Ww ? 2 * Ww - 2 - yc : yc;
        const float* p = y + ((size_t)bb * CIN + 2 * cp) * (Hh * Ww) + (size_t)yr * Ww + yc;
        v0 = p[0]; v1 = p[Hh * Ww];
    }
    g_yext2[idx] = __floats2half2_rn(v0, v1);
}

// ---------------- weight transform: wAh[br][tap][co][ci] fp16 ----------------
__global__ void wt_kernel(const float* __restrict__ w) {
    int idx = blockIdx.x * blockDim.x + threadIdx.x;
    if (idx >= NBR * 9 * COUT * CIN) return;
    int ci = idx % CIN; int t = idx / CIN;
    int co = t % COUT; t /= COUT;
    int tap = t % 9; int br = t / 9;
    g_wAh[idx] = __float2half_rn(w[(((size_t)br * COUT + co) * CIN + ci) * 9 + tap]);
}

// ---------------- xn + x fp16 transpose ----------------
__global__ void xn_kernel(const float* __restrict__ x) {
    int idx = blockIdx.x * blockDim.x + threadIdx.x;
    if (idx >= NB * 4 * Hh * Ww) return;
    int hw = idx % (Hh * Ww);
    int t = idx / (Hh * Ww);
    int g = t % 4, bb = t / 4;
    const float* xp = x + ((size_t)bb * CIN + g * 32) * (Hh * Ww) + hw;
    __half* xo = g_xh + ((size_t)bb * Hh * Ww + hw) * 128 + g * 32;
    float s = 0.f;
#pragma unroll
    for (int c = 0; c < 32; c++) {
        float v = xp[(size_t)c * Hh * Ww];
        s += v * v;
        xo[c] = __float2half_rn(v);
    }
    g_xn[idx] = sqrtf(s);
}

// ---------------- fp16 mma.sync conv, K=64 per stage ----------------
// it = qp*9 + tap (qp in 0..1, tap = kh*3+kw). A tile [128co][64ci] (LDA2=72).
// B stage s = qp*3+kh: 32 kpair rows x 178 cols, [col][kpair] (BCOL=36).
#define LDA2 72
#define BCOL 36
#define A_HALFS 9216                 // 128*72
#define B_H2 6408                    // 178*36
#define OFF_B 36864                  // bytes: 2 A stages
#define CONV_SMEM (36864 + 2 * (B_H2 * 4))   // 88128 B

__device__ __forceinline__ void stage_A(__half* Abase, int it, int tid, const __half* wbr) {
    int qp = it / 9, tap = it % 9;
    const __half* wsrc = wbr + (size_t)tap * COUT * CIN + qp * 64;
#pragma unroll
    for (int i = tid; i < 1024; i += 256) {
        int co = i >> 3, k8 = i & 7;
        cpa16(Abase + co * LDA2 + k8 * 8, wsrc + (size_t)co * CIN + k8 * 8);
    }
}

// stage piece of B stage s = qp*3+kh: ci-pair rows qp*32..+31, full EXW cols
__device__ __forceinline__ void stage_B(__half2* bt, int s, int piece, int tid,
                                        const __half2* yb2, int r, int d) {
    int qp = s / 3, kh = s % 3;
    const __half2* rowbase = yb2 + (size_t)qp * 32 * EXHW + (size_t)(r + 21 + d * (kh - 1)) * EXW;
    int lo = piece * 1899, hi = (piece == 2) ? 5696 : lo + 1899;
    for (int i = lo + tid; i < hi; i += 256) {
        int kr = i / 178, c = i - kr * 178;
        cpa4(bt + c * BCOL + kr, rowbase + (size_t)kr * EXHW + c);
    }
}

__global__ __launch_bounds__(256, 2) void conv_mma_kernel(const float* __restrict__ bias) {
    extern __shared__ __align__(16) char dsm[];
    __half* Asm = (__half*)dsm;
    __half2* Bsm = (__half2*)(dsm + OFF_B);
    __half* ep = (__half*)dsm;     // epilogue reuse

    int tid = threadIdx.x, warp = tid >> 5, lane = tid & 31;
    int gq = lane >> 2, tig = lane & 3;
    int br = blockIdx.y >> 1, bb = blockIdx.y & 1;
    int r = blockIdx.x;
    int d = c_rad[br];
    int wm = warp & 3, wn = warp >> 2;
    int ntiles = wn ? 8 : 9;
    int tbase = wn * 9;

    const __half* wbr = g_wAh + (size_t)br * 9 * COUT * CIN;
    const __half2* yb2 = g_yext2 + (size_t)bb * 64 * EXHW;

    // ldmatrix per-lane address components
    int aro = (lane & 15);
    int ako = (lane >> 4) << 3;
    int bco = (lane & 7) + ((lane >> 4) & 1) * 8;
    int bko = ((lane >> 3) & 1) * 4;

    float acc[2][9][4];
#pragma unroll
    for (int mt = 0; mt < 2; mt++)
#pragma unroll
        for (int t = 0; t < 9; t++)
#pragma unroll
            for (int u = 0; u < 4; u++) acc[mt][t][u] = 0.f;

    // prestage: full B stage 0, then A0  (groups 0, 1)
    stage_B(Bsm, 0, 0, tid, yb2, r, d);
    stage_B(Bsm, 0, 1, tid, yb2, r, d);
    stage_B(Bsm, 0, 2, tid, yb2, r, d);
    CP_COMMIT();
    stage_A(Asm, 0, tid, wbr);
    CP_COMMIT();

    for (int it = 0; it < 18; ++it) {
        int s = it / 3, p = it % 3;
        int kw = p;
        // prefetch piece p of B stage s+1
        if (s + 1 < 6) stage_B(Bsm + ((s + 1) & 1) * B_H2, s + 1, p, tid, yb2, r, d);
        CP_COMMIT();
        // prefetch A for it+1
        if (it + 1 < 18) stage_A(Asm + ((it + 1) & 1) * A_HALFS, it + 1, tid, wbr);
        CP_COMMIT();
        asm volatile("cp.async.wait_group 2;" ::: "memory");
        __syncthreads();

        uint32_t sAb = (uint32_t)__cvta_generic_to_shared(Asm + (it & 1) * A_HALFS);
        uint32_t sBb = (uint32_t)__cvta_generic_to_shared(Bsm + (s & 1) * B_H2);
        int off = 21 + d * (kw - 1);          // column offset into staged row
#pragma unroll
        for (int kk2 = 0; kk2 < 4; kk2++) {
            uint32_t a0[4], a1[4];
            ldsm_x4(a0, sAb + ((wm * 32 + aro) * LDA2 + kk2 * 16 + ako) * 2);
            ldsm_x4(a1, sAb + ((wm * 32 + 16 + aro) * LDA2 + kk2 * 16 + ako) * 2);
#pragma unroll
            for (int tp = 0; tp < 4; tp++) {
                uint32_t b[4];
                int colb = off + (tbase + 2 * tp) * 8 + bco;
                ldsm_x4(b, sBb + (colb * BCOL + kk2 * 8 + bko) * 4);
                mma16(acc[0][2 * tp], a0, b[0], b[1]);
                mma16(acc[1][2 * tp], a1, b[0], b[1]);
                mma16(acc[0][2 * tp + 1], a0, b[2], b[3]);
                mma16(acc[1][2 * tp + 1], a1, b[2], b[3]);
            }
            if (ntiles == 9) {
                uint32_t b[2];
                int colb = off + (tbase + 8) * 8 + bco;
                ldsm_x2(b, sBb + (colb * BCOL + kk2 * 8 + bko) * 4);
                mma16(acc[0][8], a0, b[0], b[1]);
                mma16(acc[1][8], a1, b[0], b[1]);
            }
        }
        __syncthreads();
    }
    asm volatile("cp.async.wait_group 0;" ::: "memory");
    __syncthreads();

    // epilogue: bias + fp16 transpose -> g_ygh[row][col][ch]
#pragma unroll
    for (int mt = 0; mt < 2; mt++) {
        int co0 = wm * 32 + mt * 16 + gq, co1 = co0 + 8;
        float bv0 = bias[br * COUT + co0], bv1 = bias[br * COUT + co1];
#pragma unroll
        for (int t = 0; t < 9; t++) {
            if (t < ntiles) {
                int col = (tbase + t) * 8 + 2 * tig;
                ep[col * 128 + co0] = __float2half(acc[mt][t][0] + bv0);
                ep[(col + 1) * 128 + co0] = __float2half(acc[mt][t][1] + bv0);
                ep[col * 128 + co1] = __float2half(acc[mt][t][2] + bv1);
                ep[(col + 1) * 128 + co1] = __float2half(acc[mt][t][3] + bv1);
            }
        }
    }
    __syncthreads();
    __half* dst = g_ygh + ((size_t)(br * NB + bb) * HP + r) * WP * 128;
    const uint4* src = (const uint4*)ep;
    for (int i = tid; i < 136 * 128 / 8; i += 256)
        ((uint4*)dst)[i] = src[i];
}

// ---------------- yn from fp16 ----------------
__global__ void yn_kernel() {
    int idx = blockIdx.x * blockDim.x + threadIdx.x;
    if (idx >= NBR * NB * 4 * HP * WP) return;
    int hw = idx % (HP * WP);
    int t = idx / (HP * WP);
    int g = t % 4; t /= 4;
    int bb = t % 2; int br = t / 2;
    const __half2* p = (const __half2*)(g_ygh + ((size_t)(br * NB + bb) * HP * WP + hw) * 128 + g * 32);
    float s = 0.f;
#pragma unroll
    for (int c = 0; c < 16; c++) {
        float2 f = __half22float2(p[c]);
        s += f.x * f.x + f.y * f.y;
    }
    g_yn[idx] = sqrtf(s);
}

// ---------------- tensor-core 81-shift correlation ----------------
#define YLD 40

__global__ __launch_bounds__(256, 3) void corr_kernel(float* __restrict__ out) {
    __shared__ __align__(16) __half Yb[2][136 * YLD];
    __shared__ float Es[8][16 * 25];

    int tid = threadIdx.x, warp = tid >> 5, lane = tid & 31;
    int gq = lane >> 2, tig = lane & 3;
    int r = blockIdx.x;
    int br = blockIdx.y;
    int zz = blockIdx.z;
    int bb = zz >> 2, g = zz & 3;
    int c0 = warp * 16;

    const __half* xb = g_xh + ((size_t)bb * Hh + r) * Ww * 128 + g * 32;
    uint32_t a[2][4];
#pragma unroll
    for (int ks = 0; ks < 2; ks++) {
        a[ks][0] = *(const uint32_t*)(xb + (size_t)(c0 + gq) * 128 + ks * 16 + 2 * tig);
        a[ks][1] = *(const uint32_t*)(xb + (size_t)(c0 + gq + 8) * 128 + ks * 16 + 2 * tig);
        a[ks][2] = *(const uint32_t*)(xb + (size_t)(c0 + gq) * 128 + ks * 16 + 8 + 2 * tig);
        a[ks][3] = *(const uint32_t*)(xb + (size_t)(c0 + gq + 8) * 128 + ks * 16 + 8 + 2 * tig);
    }

    const __half* ysrc = g_ygh + (size_t)(br * NB + bb) * HP * WP * 128 + g * 32;
    {
        const __half* rowp = ysrc + (size_t)r * WP * 128;
        for (int i = tid; i < 544; i += 256) {
            int col = i >> 2, c = i & 3;
            cpa16(&Yb[0][col * YLD + c * 8], rowp + (size_t)col * 128 + c * 8);
        }
    }
    CP_COMMIT();

    const float* xnrow = g_xn + ((size_t)bb * 4 + g) * Hh * Ww + (size_t)r * Ww + c0;
    const float* ynb = g_yn + ((size_t)(br * NB + bb) * 4 + g) * HP * WP;
    size_t ob0 = ((size_t)(bb * 24 + br * 4 + g) * 81) * (Hh * Ww) + (size_t)r * Ww + c0;

    for (int sx = 0; sx < 9; sx++) {
        if (sx < 8) {
            const __half* rowp = ysrc + (size_t)(r + sx + 1) * WP * 128;
            __half* db = Yb[(sx + 1) & 1];
            for (int i = tid; i < 544; i += 256) {
                int col = i >> 2, c = i & 3;
                cpa16(&db[col * YLD + c * 8], rowp + (size_t)col * 128 + c * 8);
            }
            CP_COMMIT();
            asm volatile("cp.async.wait_group 1;" ::: "memory");
        } else {
            asm volatile("cp.async.wait_group 0;" ::: "memory");
        }
        __syncthreads();

        const uint32_t* sB = (const uint32_t*)Yb[sx & 1];
        float e[3][4];
#pragma unroll
        for (int nt = 0; nt < 3; nt++) {
            e[nt][0] = e[nt][1] = e[nt][2] = e[nt][3] = 0.f;
            int col = c0 + nt * 8 + gq;
#pragma unroll
            for (int ks = 0; ks < 2; ks++) {
                uint32_t b0 = sB[col * 20 + tig + 8 * ks];
                uint32_t b1 = sB[col * 20 + tig + 4 + 8 * ks];
                mma16(e[nt], a[ks], b0, b1);
            }
        }
        float* Ew = Es[warp];
#pragma unroll
        for (int nt = 0; nt < 3; nt++) {
            int cc = nt * 8 + 2 * tig;
            Ew[gq * 25 + cc] = e[nt][0];
            Ew[gq * 25 + cc + 1] = e[nt][1];
            Ew[(gq + 8) * 25 + cc] = e[nt][2];
            Ew[(gq + 8) * 25 + cc + 1] = e[nt][3];
        }
        __syncwarp();
        const float* ynrow = ynb + (size_t)(r + sx) * WP + c0;
        size_t ob = ob0 + (size_t)sx * 9 * (Hh * Ww);
#pragma unroll
        for (int u = 0; u < 5; u++) {
            int idx = lane + u * 32;
            if (idx < 144) {
                int sy = idx >> 4, p = idx & 15;
                float num = Ew[p * 25 + p + sy];
                float den = fmaxf(xnrow[p] * ynrow[p + sy], 1e-8f);
                out[ob + (size_t)sy * (Hh * Ww) + p] = __fdividef(num, den);
            }
        }
        __syncthreads();
    }
}

// ---------------- launch ----------------
extern "C" void kernel_launch(void* const* d_in, const int* in_sizes, int n_in,
                              void* d_out, int out_size) {
    const float* x    = (const float*)d_in[0];
    const float* y    = (const float*)d_in[1];
    const float* wts  = (const float*)d_in[2];
    const float* bias = (const float*)d_in[3];
    float* out = (float*)d_out;

    cudaFuncSetAttribute(conv_mma_kernel,
                         cudaFuncAttributeMaxDynamicSharedMemorySize, CONV_SMEM);

    pad_kernel<<<(NB * 64 * EXHW + 255) / 256, 256>>>(y);
    wt_kernel<<<(NBR * 9 * COUT * CIN + 255) / 256, 256>>>(wts);
    xn_kernel<<<(NB * 4 * Hh * Ww + 255) / 256, 256>>>(x);
    conv_mma_kernel<<<dim3(104, 12), 256, CONV_SMEM>>>(bias);
    yn_kernel<<<(NBR * NB * 4 * HP * WP + 255) / 256, 256>>>();
    corr_kernel<<<dim3(Hh, NBR, NB * 4), 256>>>(out);
}

// round 12
// speedup vs baseline: 9.7307x; 1.0494x over previous
#include <cuda_runtime.h>
#include <cuda_fp16.h>
#include <math.h>
#include <cstdint>

#define Hh 96
#define Ww 128
#define HP 104
#define WP 136
#define CIN 128
#define COUT 128
#define NB 2
#define NBR 6
#define EXH 146            // HP + 2*21
#define EXW 178            // WP + 2*21
#define EXHW (EXH*EXW)

// -------- scratch (device globals: allocation-free) --------
__device__ __align__(16) __half g_ygh[(size_t)NBR * NB * HP * WP * 128];   // conv out [br][bb][row][col][ch]
__device__ __align__(16) float g_yn[(size_t)NBR * NB * 4 * HP * WP];
__device__ __align__(16) float g_xn[(size_t)NB * 4 * Hh * Ww];
__device__ __align__(16) __half g_xh[(size_t)NB * Hh * Ww * 128];          // x fp16 [bb][row][col][ch]
__device__ __align__(16) __half2 g_yext2[(size_t)NB * 64 * EXHW + 64];     // ci-pair fp16
__device__ __align__(16) __half g_wAh[(size_t)NBR * 9 * COUT * CIN];       // fp16 weights [br][tap][co][ci]

__constant__ int c_rad[6] = {1, 3, 5, 9, 13, 21};

__device__ __forceinline__ void mma16(float* c, const uint32_t* a, uint32_t b0, uint32_t b1) {
    asm volatile(
        "mma.sync.aligned.m16n8k16.row.col.f32.f16.f16.f32 "
        "{%0,%1,%2,%3}, {%4,%5,%6,%7}, {%8,%9}, {%0,%1,%2,%3};"
        : "+f"(c[0]), "+f"(c[1]), "+f"(c[2]), "+f"(c[3])
        : "r"(a[0]), "r"(a[1]), "r"(a[2]), "r"(a[3]), "r"(b0), "r"(b1));
}
__device__ __forceinline__ void ldsm_x4(uint32_t* r, uint32_t addr) {
    asm volatile("ldmatrix.sync.aligned.m8n8.x4.shared.b16 {%0,%1,%2,%3}, [%4];"
                 : "=r"(r[0]), "=r"(r[1]), "=r"(r[2]), "=r"(r[3]) : "r"(addr));
}
__device__ __forceinline__ void ldsm_x2(uint32_t* r, uint32_t addr) {
    asm volatile("ldmatrix.sync.aligned.m8n8.x2.shared.b16 {%0,%1}, [%2];"
                 : "=r"(r[0]), "=r"(r[1]) : "r"(addr));
}
__device__ __forceinline__ void cpa16(void* dst, const void* src) {
    uint32_t d = (uint32_t)__cvta_generic_to_shared(dst);
    asm volatile("cp.async.cg.shared.global [%0], [%1], 16;" :: "r"(d), "l"(src));
}
__device__ __forceinline__ void cpa4(void* dst, const void* src) {
    uint32_t d = (uint32_t)__cvta_generic_to_shared(dst);
    asm volatile("cp.async.ca.shared.global [%0], [%1], 4;" :: "r"(d), "l"(src));
}
#define CP_COMMIT() asm volatile("cp.async.commit_group;" ::: "memory")

// ---------------- y_ext fp16 half2 (ci pairs): reflect pad + 21 zero halo ----------------
__global__ void pad_kernel(const float* __restrict__ y) {
    int idx = blockIdx.x * blockDim.x + threadIdx.x;
    if (idx >= NB * 64 * EXHW) return;
    int c = idx % EXW; int t = idx / EXW;
    int rr = t % EXH; t /= EXH;
    int cp = t % 64; int bb = t / 64;
    int pr = rr - 21, pc = c - 21;
    float v0 = 0.f, v1 = 0.f;
    if (pr >= 0 && pr < HP && pc >= 0 && pc < WP) {
        int yr = pr - 4; yr = yr < 0 ? -yr : yr; yr = yr >= Hh ? 2 * Hh - 2 - yr : yr;
        int yc = pc - 4; yc = yc < 0 ? -yc : yc; yc = yc >= Ww ? 2 * Ww - 2 - yc : yc;
        const float* p = y + ((size_t)bb * CIN + 2 * cp) * (Hh * Ww) + (size_t)yr * Ww + yc;
        v0 = p[0]; v1 = p[Hh * Ww];
    }
    g_yext2[idx] = __floats2half2_rn(v0, v1);
}

// ---------------- weight transform: wAh[br][tap][co][ci] fp16 ----------------
__global__ void wt_kernel(const float* __restrict__ w) {
    int idx = blockIdx.x * blockDim.x + threadIdx.x;
    if (idx >= NBR * 9 * COUT * CIN) return;
    int ci = idx % CIN; int t = idx / CIN;
    int co = t % COUT; t /= COUT;
    int tap = t % 9; int br = t / 9;
    g_wAh[idx] = __float2half_rn(w[(((size_t)br * COUT + co) * CIN + ci) * 9 + tap]);
}

// ---------------- xn + x fp16 transpose ----------------
__global__ void xn_kernel(const float* __restrict__ x) {
    int idx = blockIdx.x * blockDim.x + threadIdx.x;
    if (idx >= NB * 4 * Hh * Ww) return;
    int hw = idx % (Hh * Ww);
    int t = idx / (Hh * Ww);
    int g = t % 4, bb = t / 4;
    const float* xp = x + ((size_t)bb * CIN + g * 32) * (Hh * Ww) + hw;
    __half* xo = g_xh + ((size_t)bb * Hh * Ww + hw) * 128 + g * 32;
    float s = 0.f;
#pragma unroll
    for (int c = 0; c < 32; c++) {
        float v = xp[(size_t)c * Hh * Ww];
        s += v * v;
        xo[c] = __float2half_rn(v);
    }
    g_xn[idx] = sqrtf(s);
}

// ---------------- fp16 mma.sync conv, K=64 per stage ----------------
#define LDA2 72
#define BCOL 36
#define A_HALFS 9216                 // 128*72
#define B_H2 6408                    // 178*36
#define OFF_B 36864                  // bytes: 2 A stages
#define CONV_SMEM (36864 + 2 * (B_H2 * 4))   // 88128 B

__device__ __forceinline__ void stage_A(__half* Abase, int it, int tid, const __half* wbr) {
    int qp = it / 9, tap = it % 9;
    const __half* wsrc = wbr + (size_t)tap * COUT * CIN + qp * 64;
#pragma unroll
    for (int i = tid; i < 1024; i += 256) {
        int co = i >> 3, k8 = i & 7;
        cpa16(Abase + co * LDA2 + k8 * 8, wsrc + (size_t)co * CIN + k8 * 8);
    }
}

// stage piece of B stage s = qp*3+kh. Div-free: thread t -> kr = t>>3, c = (t&7)+8j.
__device__ __forceinline__ void stage_B(__half2* bt, int s, int piece, int tid,
                                        const __half2* yb2, int r, int d) {
    int qp = s / 3, kh = s % 3;
    int kr = tid >> 3, c0 = tid & 7;
    const __half2* rowp = yb2 + (size_t)(qp * 32 + kr) * EXHW
                        + (size_t)(r + 21 + d * (kh - 1)) * EXW;
    __half2* dst = bt + kr;
    if (piece < 2) {
        int jlo = piece * 8;
#pragma unroll
        for (int j = 0; j < 8; j++) {
            int c = c0 + 8 * (jlo + j);
            cpa4(dst + c * BCOL, rowp + c);
        }
    } else {
#pragma unroll
        for (int j = 16; j < 23; j++) {
            int c = c0 + 8 * j;
            if (c < EXW) cpa4(dst + c * BCOL, rowp + c);
        }
    }
}

__global__ __launch_bounds__(256, 2) void conv_mma_kernel(const float* __restrict__ bias) {
    extern __shared__ __align__(16) char dsm[];
    __half* Asm = (__half*)dsm;
    __half2* Bsm = (__half2*)(dsm + OFF_B);
    __half* ep = (__half*)dsm;     // epilogue reuse

    int tid = threadIdx.x, warp = tid >> 5, lane = tid & 31;
    int gq = lane >> 2, tig = lane & 3;
    int br = blockIdx.y >> 1, bb = blockIdx.y & 1;
    int r = blockIdx.x;
    int d = c_rad[br];
    int wm = warp & 3, wn = warp >> 2;
    int ntiles = wn ? 8 : 9;
    int tbase = wn * 9;

    const __half* wbr = g_wAh + (size_t)br * 9 * COUT * CIN;
    const __half2* yb2 = g_yext2 + (size_t)bb * 64 * EXHW;

    int aro = (lane & 15);
    int ako = (lane >> 4) << 3;
    int bco = (lane & 7) + ((lane >> 4) & 1) * 8;
    int bko = ((lane >> 3) & 1) * 4;

    float acc[2][9][4];
#pragma unroll
    for (int mt = 0; mt < 2; mt++)
#pragma unroll
        for (int t = 0; t < 9; t++)
#pragma unroll
            for (int u = 0; u < 4; u++) acc[mt][t][u] = 0.f;

    // prestage: full B stage 0 + A0, single group 0
    stage_B(Bsm, 0, 0, tid, yb2, r, d);
    stage_B(Bsm, 0, 1, tid, yb2, r, d);
    stage_B(Bsm, 0, 2, tid, yb2, r, d);
    stage_A(Asm, 0, tid, wbr);
    CP_COMMIT();

    for (int it = 0; it < 18; ++it) {
        int s = it / 3, p = it % 3;
        int kw = p;
        // one group per iter: B piece p of stage s+1, plus A(it+1)
        if (s + 1 < 6) stage_B(Bsm + ((s + 1) & 1) * B_H2, s + 1, p, tid, yb2, r, d);
        if (it + 1 < 18) stage_A(Asm + ((it + 1) & 1) * A_HALFS, it + 1, tid, wbr);
        CP_COMMIT();
        asm volatile("cp.async.wait_group 1;" ::: "memory");
        __syncthreads();

        uint32_t sAb = (uint32_t)__cvta_generic_to_shared(Asm + (it & 1) * A_HALFS);
        uint32_t sBb = (uint32_t)__cvta_generic_to_shared(Bsm + (s & 1) * B_H2);
        int off = 21 + d * (kw - 1);
#pragma unroll
        for (int kk2 = 0; kk2 < 4; kk2++) {
            uint32_t a0[4], a1[4];
            ldsm_x4(a0, sAb + ((wm * 32 + aro) * LDA2 + kk2 * 16 + ako) * 2);
            ldsm_x4(a1, sAb + ((wm * 32 + 16 + aro) * LDA2 + kk2 * 16 + ako) * 2);
#pragma unroll
            for (int tp = 0; tp < 4; tp++) {
                uint32_t b[4];
                int colb = off + (tbase + 2 * tp) * 8 + bco;
                ldsm_x4(b, sBb + (colb * BCOL + kk2 * 8 + bko) * 4);
                mma16(acc[0][2 * tp], a0, b[0], b[1]);
                mma16(acc[1][2 * tp], a1, b[0], b[1]);
                mma16(acc[0][2 * tp + 1], a0, b[2], b[3]);
                mma16(acc[1][2 * tp + 1], a1, b[2], b[3]);
            }
            if (ntiles == 9) {
                uint32_t b[2];
                int colb = off + (tbase + 8) * 8 + bco;
                ldsm_x2(b, sBb + (colb * BCOL + kk2 * 8 + bko) * 4);
                mma16(acc[0][8], a0, b[0], b[1]);
                mma16(acc[1][8], a1, b[0], b[1]);
            }
        }
        __syncthreads();
    }
    asm volatile("cp.async.wait_group 0;" ::: "memory");
    __syncthreads();

    // epilogue: bias + fp16 transpose -> g_ygh[row][col][ch]
#pragma unroll
    for (int mt = 0; mt < 2; mt++) {
        int co0 = wm * 32 + mt * 16 + gq, co1 = co0 + 8;
        float bv0 = bias[br * COUT + co0], bv1 = bias[br * COUT + co1];
#pragma unroll
        for (int t = 0; t < 9; t++) {
            if (t < ntiles) {
                int col = (tbase + t) * 8 + 2 * tig;
                ep[col * 128 + co0] = __float2half(acc[mt][t][0] + bv0);
                ep[(col + 1) * 128 + co0] = __float2half(acc[mt][t][1] + bv0);
                ep[col * 128 + co1] = __float2half(acc[mt][t][2] + bv1);
                ep[(col + 1) * 128 + co1] = __float2half(acc[mt][t][3] + bv1);
            }
        }
    }
    __syncthreads();
    __half* dst = g_ygh + ((size_t)(br * NB + bb) * HP + r) * WP * 128;
    const uint4* src = (const uint4*)ep;
    for (int i = tid; i < 136 * 128 / 8; i += 256)
        ((uint4*)dst)[i] = src[i];
}

// ---------------- yn from fp16 ----------------
__global__ void yn_kernel() {
    int idx = blockIdx.x * blockDim.x + threadIdx.x;
    if (idx >= NBR * NB * 4 * HP * WP) return;
    int hw = idx % (HP * WP);
    int t = idx / (HP * WP);
    int g = t % 4; t /= 4;
    int bb = t % 2; int br = t / 2;
    const __half2* p = (const __half2*)(g_ygh + ((size_t)(br * NB + bb) * HP * WP + hw) * 128 + g * 32);
    float s = 0.f;
#pragma unroll
    for (int c = 0; c < 16; c++) {
        float2 f = __half22float2(p[c]);
        s += f.x * f.x + f.y * f.y;
    }
    g_yn[idx] = sqrtf(s);
}

// ---------------- tensor-core 81-shift correlation ----------------
#define YLD 40

__global__ __launch_bounds__(256, 3) void corr_kernel(float* __restrict__ out) {
    __shared__ __align__(16) __half Yb[2][136 * YLD];
    __shared__ float Es[8][16 * 25];

    int tid = threadIdx.x, warp = tid >> 5, lane = tid & 31;
    int gq = lane >> 2, tig = lane & 3;
    int r = blockIdx.x;
    int br = blockIdx.y;
    int zz = blockIdx.z;
    int bb = zz >> 2, g = zz & 3;
    int c0 = warp * 16;

    const __half* xb = g_xh + ((size_t)bb * Hh + r) * Ww * 128 + g * 32;
    uint32_t a[2][4];
#pragma unroll
    for (int ks = 0; ks < 2; ks++) {
        a[ks][0] = *(const uint32_t*)(xb + (size_t)(c0 + gq) * 128 + ks * 16 + 2 * tig);
        a[ks][1] = *(const uint32_t*)(xb + (size_t)(c0 + gq + 8) * 128 + ks * 16 + 2 * tig);
        a[ks][2] = *(const uint32_t*)(xb + (size_t)(c0 + gq) * 128 + ks * 16 + 8 + 2 * tig);
        a[ks][3] = *(const uint32_t*)(xb + (size_t)(c0 + gq + 8) * 128 + ks * 16 + 8 + 2 * tig);
    }

    const __half* ysrc = g_ygh + (size_t)(br * NB + bb) * HP * WP * 128 + g * 32;
    {
        const __half* rowp = ysrc + (size_t)r * WP * 128;
        for (int i = tid; i < 544; i += 256) {
            int col = i >> 2, c = i & 3;
            cpa16(&Yb[0][col * YLD + c * 8], rowp + (size_t)col * 128 + c * 8);
        }
    }
    CP_COMMIT();

    const float* xnrow = g_xn + ((size_t)bb * 4 + g) * Hh * Ww + (size_t)r * Ww + c0;
    const float* ynb = g_yn + ((size_t)(br * NB + bb) * 4 + g) * HP * WP;
    size_t ob0 = ((size_t)(bb * 24 + br * 4 + g) * 81) * (Hh * Ww) + (size_t)r * Ww + c0;

    for (int sx = 0; sx < 9; sx++) {
        if (sx < 8) {
            const __half* rowp = ysrc + (size_t)(r + sx + 1) * WP * 128;
            __half* db = Yb[(sx + 1) & 1];
            for (int i = tid; i < 544; i += 256) {
                int col = i >> 2, c = i & 3;
                cpa16(&db[col * YLD + c * 8], rowp + (size_t)col * 128 + c * 8);
            }
            CP_COMMIT();
            asm volatile("cp.async.wait_group 1;" ::: "memory");
        } else {
            asm volatile("cp.async.wait_group 0;" ::: "memory");
        }
        __syncthreads();

        const uint32_t* sB = (const uint32_t*)Yb[sx & 1];
        float e[3][4];
#pragma unroll
        for (int nt = 0; nt < 3; nt++) {
            e[nt][0] = e[nt][1] = e[nt][2] = e[nt][3] = 0.f;
            int col = c0 + nt * 8 + gq;
#pragma unroll
            for (int ks = 0; ks < 2; ks++) {
                uint32_t b0 = sB[col * 20 + tig + 8 * ks];
                uint32_t b1 = sB[col * 20 + tig + 4 + 8 * ks];
                mma16(e[nt], a[ks], b0, b1);
            }
        }
        float* Ew = Es[warp];
#pragma unroll
        for (int nt = 0; nt < 3; nt++) {
            int cc = nt * 8 + 2 * tig;
            Ew[gq * 25 + cc] = e[nt][0];
            Ew[gq * 25 + cc + 1] = e[nt][1];
            Ew[(gq + 8) * 25 + cc] = e[nt][2];
            Ew[(gq + 8) * 25 + cc + 1] = e[nt][3];
        }
        __syncwarp();
        // extract band, normalize, store as float2 (72 items)
        const float* ynrow = ynb + (size_t)(r + sx) * WP + c0;
        size_t ob = ob0 + (size_t)sx * 9 * (Hh * Ww);
#pragma unroll
        for (int u = 0; u < 3; u++) {
            int idx = lane + u * 32;
            if (idx < 72) {
                int sy = idx >> 3, pp = (idx & 7) * 2;
                float n0 = Ew[pp * 25 + pp + sy];
                float n1 = Ew[pp * 25 + pp + sy + 26];
                float d0 = fmaxf(xnrow[pp] * ynrow[pp + sy], 1e-8f);
                float d1 = fmaxf(xnrow[pp + 1] * ynrow[pp + 1 + sy], 1e-8f);
                *(float2*)&out[ob + (size_t)sy * (Hh * Ww) + pp] =
                    make_float2(__fdividef(n0, d0), __fdividef(n1, d1));
            }
        }
        __syncthreads();
    }
}

// ---------------- launch ----------------
extern "C" void kernel_launch(void* const* d_in, const int* in_sizes, int n_in,
                              void* d_out, int out_size) {
    const float* x    = (const float*)d_in[0];
    const float* y    = (const float*)d_in[1];
    const float* wts  = (const float*)d_in[2];
    const float* bias = (const float*)d_in[3];
    float* out = (float*)d_out;

    cudaFuncSetAttribute(conv_mma_kernel,
                         cudaFuncAttributeMaxDynamicSharedMemorySize, CONV_SMEM);

    pad_kernel<<<(NB * 64 * EXHW + 255) / 256, 256>>>(y);
    wt_kernel<<<(NBR * 9 * COUT * CIN + 255) / 256, 256>>>(wts);
    xn_kernel<<<(NB * 4 * Hh * Ww + 255) / 256, 256>>>(x);
    conv_mma_kernel<<<dim3(104, 12), 256, CONV_SMEM>>>(bias);
    yn_kernel<<<(NBR * NB * 4 * HP * WP + 255) / 256, 256>>>();
    corr_kernel<<<dim3(Hh, NBR, NB * 4), 256>>>(out);
}

// round 13
// speedup vs baseline: 10.1731x; 1.0455x over previous
#include <cuda_runtime.h>
#include <cuda_fp16.h>
#include <math.h>
#include <cstdint>

#define Hh 96
#define Ww 128
#define HP 104
#define WP 136
#define CIN 128
#define COUT 128
#define NB 2
#define NBR 6
#define EXH 146            // HP + 2*21
#define EXW 178            // WP + 2*21
#define EXHW (EXH*EXW)

// -------- scratch (device globals: allocation-free) --------
__device__ __align__(16) __half g_ygh[(size_t)NBR * NB * HP * WP * 128];   // conv out [br][bb][row][col][ch]
__device__ __align__(16) float g_yn[(size_t)NBR * NB * 4 * HP * WP];
__device__ __align__(16) float g_xn[(size_t)NB * 4 * Hh * Ww];
__device__ __align__(16) __half g_xh[(size_t)NB * Hh * Ww * 128];          // x fp16 [bb][row][col][ch]
__device__ __align__(16) __half2 g_yext2[(size_t)NB * 64 * EXHW + 64];     // ci-pair fp16
__device__ __align__(16) __half g_wAh[(size_t)NBR * 9 * COUT * CIN];       // fp16 weights [br][tap][co][ci]

__constant__ int c_rad[6] = {1, 3, 5, 9, 13, 21};

__device__ __forceinline__ void mma16(float* c, const uint32_t* a, uint32_t b0, uint32_t b1) {
    asm volatile(
        "mma.sync.aligned.m16n8k16.row.col.f32.f16.f16.f32 "
        "{%0,%1,%2,%3}, {%4,%5,%6,%7}, {%8,%9}, {%0,%1,%2,%3};"
        : "+f"(c[0]), "+f"(c[1]), "+f"(c[2]), "+f"(c[3])
        : "r"(a[0]), "r"(a[1]), "r"(a[2]), "r"(a[3]), "r"(b0), "r"(b1));
}
__device__ __forceinline__ void ldsm_x4(uint32_t* r, uint32_t addr) {
    asm volatile("ldmatrix.sync.aligned.m8n8.x4.shared.b16 {%0,%1,%2,%3}, [%4];"
                 : "=r"(r[0]), "=r"(r[1]), "=r"(r[2]), "=r"(r[3]) : "r"(addr));
}
__device__ __forceinline__ void ldsm_x2(uint32_t* r, uint32_t addr) {
    asm volatile("ldmatrix.sync.aligned.m8n8.x2.shared.b16 {%0,%1}, [%2];"
                 : "=r"(r[0]), "=r"(r[1]) : "r"(addr));
}
__device__ __forceinline__ void cpa16(void* dst, const void* src) {
    uint32_t d = (uint32_t)__cvta_generic_to_shared(dst);
    asm volatile("cp.async.cg.shared.global [%0], [%1], 16;" :: "r"(d), "l"(src));
}
__device__ __forceinline__ void cpa4(void* dst, const void* src) {
    uint32_t d = (uint32_t)__cvta_generic_to_shared(dst);
    asm volatile("cp.async.ca.shared.global [%0], [%1], 4;" :: "r"(d), "l"(src));
}
#define CP_COMMIT() asm volatile("cp.async.commit_group;" ::: "memory")
#define CP_WAIT0()  asm volatile("cp.async.wait_group 0;" ::: "memory")

// ---------------- y_ext fp16 half2 (ci pairs): reflect pad + 21 zero halo ----------------
__global__ void pad_kernel(const float* __restrict__ y) {
    int idx = blockIdx.x * blockDim.x + threadIdx.x;
    if (idx >= NB * 64 * EXHW) return;
    int c = idx % EXW; int t = idx / EXW;
    int rr = t % EXH; t /= EXH;
    int cp = t % 64; int bb = t / 64;
    int pr = rr - 21, pc = c - 21;
    float v0 = 0.f, v1 = 0.f;
    if (pr >= 0 && pr < HP && pc >= 0 && pc < WP) {
        int yr = pr - 4; yr = yr < 0 ? -yr : yr; yr = yr >= Hh ? 2 * Hh - 2 - yr : yr;
        int yc = pc - 4; yc = yc < 0 ? -yc : yc; yc = yc >= Ww ? 2 * Ww - 2 - yc : yc;
        const float* p = y + ((size_t)bb * CIN + 2 * cp) * (Hh * Ww) + (size_t)yr * Ww + yc;
        v0 = p[0]; v1 = p[Hh * Ww];
    }
    g_yext2[idx] = __floats2half2_rn(v0, v1);
}

// ---------------- weight transform: wAh[br][tap][co][ci] fp16 ----------------
__global__ void wt_kernel(const float* __restrict__ w) {
    int idx = blockIdx.x * blockDim.x + threadIdx.x;
    if (idx >= NBR * 9 * COUT * CIN) return;
    int ci = idx % CIN; int t = idx / CIN;
    int co = t % COUT; t /= COUT;
    int tap = t % 9; int br = t / 9;
    g_wAh[idx] = __float2half_rn(w[(((size_t)br * COUT + co) * CIN + ci) * 9 + tap]);
}

// ---------------- xn + x fp16 transpose ----------------
__global__ void xn_kernel(const float* __restrict__ x) {
    int idx = blockIdx.x * blockDim.x + threadIdx.x;
    if (idx >= NB * 4 * Hh * Ww) return;
    int hw = idx % (Hh * Ww);
    int t = idx / (Hh * Ww);
    int g = t % 4, bb = t / 4;
    const float* xp = x + ((size_t)bb * CIN + g * 32) * (Hh * Ww) + hw;
    __half* xo = g_xh + ((size_t)bb * Hh * Ww + hw) * 128 + g * 32;
    float s = 0.f;
#pragma unroll
    for (int c = 0; c < 32; c++) {
        float v = xp[(size_t)c * Hh * Ww];
        s += v * v;
        xo[c] = __float2half_rn(v);
    }
    g_xn[idx] = sqrtf(s);
}

// ---------------- fp16 mma.sync conv, K=64 per stage ----------------
#define LDA2 72
#define BCOL 36
#define A_HALFS 9216                 // 128*72
#define B_H2 6408                    // 178*36
#define OFF_B 36864                  // bytes: 2 A stages
#define CONV_SMEM (36864 + 2 * (B_H2 * 4))   // 88128 B

__device__ __forceinline__ void stage_A(__half* Abase, int it, int tid, const __half* wbr) {
    int qp = it / 9, tap = it % 9;
    const __half* wsrc = wbr + (size_t)tap * COUT * CIN + qp * 64;
#pragma unroll
    for (int i = tid; i < 1024; i += 256) {
        int co = i >> 3, k8 = i & 7;
        cpa16(Abase + co * LDA2 + k8 * 8, wsrc + (size_t)co * CIN + k8 * 8);
    }
}

// stage piece of B stage s = qp*3+kh. Div-free: thread t -> kr = t>>3, c = (t&7)+8j.
__device__ __forceinline__ void stage_B(__half2* bt, int s, int piece, int tid,
                                        const __half2* yb2, int r, int d) {
    int qp = s / 3, kh = s % 3;
    int kr = tid >> 3, c0 = tid & 7;
    const __half2* rowp = yb2 + (size_t)(qp * 32 + kr) * EXHW
                        + (size_t)(r + 21 + d * (kh - 1)) * EXW;
    __half2* dst = bt + kr;
    if (piece < 2) {
        int jlo = piece * 8;
#pragma unroll
        for (int j = 0; j < 8; j++) {
            int c = c0 + 8 * (jlo + j);
            cpa4(dst + c * BCOL, rowp + c);
        }
    } else {
#pragma unroll
        for (int j = 16; j < 23; j++) {
            int c = c0 + 8 * j;
            if (c < EXW) cpa4(dst + c * BCOL, rowp + c);
        }
    }
}

__global__ __launch_bounds__(256, 2) void conv_mma_kernel(const float* __restrict__ bias) {
    extern __shared__ __align__(16) char dsm[];
    __half* Asm = (__half*)dsm;
    __half2* Bsm = (__half2*)(dsm + OFF_B);
    __half* ep = (__half*)dsm;     // epilogue reuse

    int tid = threadIdx.x, warp = tid >> 5, lane = tid & 31;
    int gq = lane >> 2, tig = lane & 3;
    int br = blockIdx.y >> 1, bb = blockIdx.y & 1;
    int r = blockIdx.x;
    int d = c_rad[br];
    int wm = warp & 3, wn = warp >> 2;
    int ntiles = wn ? 8 : 9;
    int tbase = wn * 9;

    const __half* wbr = g_wAh + (size_t)br * 9 * COUT * CIN;
    const __half2* yb2 = g_yext2 + (size_t)bb * 64 * EXHW;

    int aro = (lane & 15);
    int ako = (lane >> 4) << 3;
    int bco = (lane & 7) + ((lane >> 4) & 1) * 8;
    int bko = ((lane >> 3) & 1) * 4;

    float acc[2][9][4];
#pragma unroll
    for (int mt = 0; mt < 2; mt++)
#pragma unroll
        for (int t = 0; t < 9; t++)
#pragma unroll
            for (int u = 0; u < 4; u++) acc[mt][t][u] = 0.f;

    // prestage: full B stage 0 + A0, group 0
    stage_B(Bsm, 0, 0, tid, yb2, r, d);
    stage_B(Bsm, 0, 1, tid, yb2, r, d);
    stage_B(Bsm, 0, 2, tid, yb2, r, d);
    stage_A(Asm, 0, tid, wbr);
    CP_COMMIT();

    for (int it = 0; it < 18; ++it) {
        int s = it / 3, p = it % 3;
        int kw = p;
        CP_WAIT0();
        __syncthreads();

        uint32_t sAb = (uint32_t)__cvta_generic_to_shared(Asm + (it & 1) * A_HALFS);
        uint32_t sBb = (uint32_t)__cvta_generic_to_shared(Bsm + (s & 1) * B_H2);
        int off = 21 + d * (kw - 1);

        auto kk2_block = [&](int kk2) {
            uint32_t a0[4], a1[4];
            ldsm_x4(a0, sAb + ((wm * 32 + aro) * LDA2 + kk2 * 16 + ako) * 2);
            ldsm_x4(a1, sAb + ((wm * 32 + 16 + aro) * LDA2 + kk2 * 16 + ako) * 2);
#pragma unroll
            for (int tp = 0; tp < 4; tp++) {
                uint32_t b[4];
                int colb = off + (tbase + 2 * tp) * 8 + bco;
                ldsm_x4(b, sBb + (colb * BCOL + kk2 * 8 + bko) * 4);
                mma16(acc[0][2 * tp], a0, b[0], b[1]);
                mma16(acc[1][2 * tp], a1, b[0], b[1]);
                mma16(acc[0][2 * tp + 1], a0, b[2], b[3]);
                mma16(acc[1][2 * tp + 1], a1, b[2], b[3]);
            }
            if (ntiles == 9) {
                uint32_t b[2];
                int colb = off + (tbase + 8) * 8 + bco;
                ldsm_x2(b, sBb + (colb * BCOL + kk2 * 8 + bko) * 4);
                mma16(acc[0][8], a0, b[0], b[1]);
                mma16(acc[1][8], a1, b[0], b[1]);
            }
        };

        kk2_block(0);
        // stage next (hidden under remaining tensor work)
        if (s + 1 < 6) stage_B(Bsm + ((s + 1) & 1) * B_H2, s + 1, p, tid, yb2, r, d);
        if (it + 1 < 18) stage_A(Asm + ((it + 1) & 1) * A_HALFS, it + 1, tid, wbr);
        CP_COMMIT();
        kk2_block(1);
        kk2_block(2);
        kk2_block(3);
    }
    CP_WAIT0();
    __syncthreads();

    // epilogue: bias + fp16 transpose -> g_ygh[row][col][ch]
#pragma unroll
    for (int mt = 0; mt < 2; mt++) {
        int co0 = wm * 32 + mt * 16 + gq, co1 = co0 + 8;
        float bv0 = bias[br * COUT + co0], bv1 = bias[br * COUT + co1];
#pragma unroll
        for (int t = 0; t < 9; t++) {
            if (t < ntiles) {
                int col = (tbase + t) * 8 + 2 * tig;
                ep[col * 128 + co0] = __float2half(acc[mt][t][0] + bv0);
                ep[(col + 1) * 128 + co0] = __float2half(acc[mt][t][1] + bv0);
                ep[col * 128 + co1] = __float2half(acc[mt][t][2] + bv1);
                ep[(col + 1) * 128 + co1] = __float2half(acc[mt][t][3] + bv1);
            }
        }
    }
    __syncthreads();
    __half* dst = g_ygh + ((size_t)(br * NB + bb) * HP + r) * WP * 128;
    const uint4* src = (const uint4*)ep;
    for (int i = tid; i < 136 * 128 / 8; i += 256)
        ((uint4*)dst)[i] = src[i];

    // fused yn: 136 px x 4 groups from the row already in smem
    for (int i = tid; i < 544; i += 256) {
        int col = i >> 2, g = i & 3;
        const __half2* pp = (const __half2*)(ep + col * 128 + g * 32);
        float s = 0.f;
#pragma unroll
        for (int k = 0; k < 16; k++) {
            int kk = (k + col) & 15;                 // rotate start: avoid bank conflicts
            float2 f = __half22float2(pp[kk]);
            s += f.x * f.x + f.y * f.y;
        }
        g_yn[(((size_t)br * NB + bb) * 4 + g) * HP * WP + (size_t)r * WP + col] = sqrtf(s);
    }
}

// ---------------- tensor-core 81-shift correlation ----------------
#define YLD 40

__global__ __launch_bounds__(256, 3) void corr_kernel(float* __restrict__ out) {
    __shared__ __align__(16) __half Yb[2][136 * YLD];
    __shared__ float Es[8][16 * 25];

    int tid = threadIdx.x, warp = tid >> 5, lane = tid & 31;
    int gq = lane >> 2, tig = lane & 3;
    int r = blockIdx.x;
    int br = blockIdx.y;
    int zz = blockIdx.z;
    int bb = zz >> 2, g = zz & 3;
    int c0 = warp * 16;

    const __half* xb = g_xh + ((size_t)bb * Hh + r) * Ww * 128 + g * 32;
    uint32_t a[2][4];
#pragma unroll
    for (int ks = 0; ks < 2; ks++) {
        a[ks][0] = *(const uint32_t*)(xb + (size_t)(c0 + gq) * 128 + ks * 16 + 2 * tig);
        a[ks][1] = *(const uint32_t*)(xb + (size_t)(c0 + gq + 8) * 128 + ks * 16 + 2 * tig);
        a[ks][2] = *(const uint32_t*)(xb + (size_t)(c0 + gq) * 128 + ks * 16 + 8 + 2 * tig);
        a[ks][3] = *(const uint32_t*)(xb + (size_t)(c0 + gq + 8) * 128 + ks * 16 + 8 + 2 * tig);
    }

    const __half* ysrc = g_ygh + (size_t)(br * NB + bb) * HP * WP * 128 + g * 32;
    {
        const __half* rowp = ysrc + (size_t)r * WP * 128;
        for (int i = tid; i < 544; i += 256) {
            int col = i >> 2, c = i & 3;
            cpa16(&Yb[0][col * YLD + c * 8], rowp + (size_t)col * 128 + c * 8);
        }
    }
    CP_COMMIT();

    const float* xnrow = g_xn + ((size_t)bb * 4 + g) * Hh * Ww + (size_t)r * Ww + c0;
    const float* ynb = g_yn + ((size_t)(br * NB + bb) * 4 + g) * HP * WP;
    size_t ob0 = ((size_t)(bb * 24 + br * 4 + g) * 81) * (Hh * Ww) + (size_t)r * Ww + c0;

    for (int sx = 0; sx < 9; sx++) {
        CP_WAIT0();
        __syncthreads();

        const uint32_t* sB = (const uint32_t*)Yb[sx & 1];
        // preload all 12 B fragments
        uint32_t b0r[3][2], b1r[3][2];
#pragma unroll
        for (int nt = 0; nt < 3; nt++) {
            int col = c0 + nt * 8 + gq;
#pragma unroll
            for (int ks = 0; ks < 2; ks++) {
                b0r[nt][ks] = sB[col * 20 + tig + 8 * ks];
                b1r[nt][ks] = sB[col * 20 + tig + 4 + 8 * ks];
            }
        }
        // stage next row (hidden under mma)
        if (sx < 8) {
            const __half* rowp = ysrc + (size_t)(r + sx + 1) * WP * 128;
            __half* db = Yb[(sx + 1) & 1];
            for (int i = tid; i < 544; i += 256) {
                int col = i >> 2, c = i & 3;
                cpa16(&db[col * YLD + c * 8], rowp + (size_t)col * 128 + c * 8);
            }
        }
        CP_COMMIT();

        float e[3][4];
#pragma unroll
        for (int nt = 0; nt < 3; nt++) {
            e[nt][0] = e[nt][1] = e[nt][2] = e[nt][3] = 0.f;
#pragma unroll
            for (int ks = 0; ks < 2; ks++)
                mma16(e[nt], a[ks], b0r[nt][ks], b1r[nt][ks]);
        }
        float* Ew = Es[warp];
#pragma unroll
        for (int nt = 0; nt < 3; nt++) {
            int cc = nt * 8 + 2 * tig;
            Ew[gq * 25 + cc] = e[nt][0];
            Ew[gq * 25 + cc + 1] = e[nt][1];
            Ew[(gq + 8) * 25 + cc] = e[nt][2];
            Ew[(gq + 8) * 25 + cc + 1] = e[nt][3];
        }
        __syncwarp();
        const float* ynrow = ynb + (size_t)(r + sx) * WP + c0;
        size_t ob = ob0 + (size_t)sx * 9 * (Hh * Ww);
#pragma unroll
        for (int u = 0; u < 3; u++) {
            int idx = lane + u * 32;
            if (idx < 72) {
                int sy = idx >> 3, pp = (idx & 7) * 2;
                float n0 = Ew[pp * 25 + pp + sy];
                float n1 = Ew[pp * 25 + pp + sy + 26];
                float d0 = fmaxf(xnrow[pp] * ynrow[pp + sy], 1e-8f);
                float d1 = fmaxf(xnrow[pp + 1] * ynrow[pp + 1 + sy], 1e-8f);
                *(float2*)&out[ob + (size_t)sy * (Hh * Ww) + pp] =
                    make_float2(__fdividef(n0, d0), __fdividef(n1, d1));
            }
        }
        __syncwarp();
    }
}

// ---------------- launch ----------------
extern "C" void kernel_launch(void* const* d_in, const int* in_sizes, int n_in,
                              void* d_out, int out_size) {
    const float* x    = (const float*)d_in[0];
    const float* y    = (const float*)d_in[1];
    const float* wts  = (const float*)d_in[2];
    const float* bias = (const float*)d_in[3];
    float* out = (float*)d_out;

    cudaFuncSetAttribute(conv_mma_kernel,
                         cudaFuncAttributeMaxDynamicSharedMemorySize, CONV_SMEM);

    pad_kernel<<<(NB * 64 * EXHW + 255) / 256, 256>>>(y);
    wt_kernel<<<(NBR * 9 * COUT * CIN + 255) / 256, 256>>>(wts);
    xn_kernel<<<(NB * 4 * Hh * Ww + 255) / 256, 256>>>(x);
    conv_mma_kernel<<<dim3(104, 12), 256, CONV_SMEM>>>(bias);
    corr_kernel<<<dim3(Hh, NBR, NB * 4), 256>>>(out);
}